// round 2
// baseline (speedup 1.0000x reference)
#include <cuda_runtime.h>
#include <math.h>

#define Bn 32
#define Hn 1024
#define Sn 1024
#define TH 128
#define TS 128
#define KT 32

// scratch (device globals: no allocation allowed)
__device__ float g_A1[Bn * Hn];
__device__ float g_logits[Bn * Sn];
__device__ float g_scores[Bn * Sn];

// ---------------------------------------------------------------------------
// Kernel 1: A1[b,h] = bias[h] + sum_k hidden[b,k] * W[h,k]   (W1 = W[:, :H])
// one warp per (b,h)
// ---------------------------------------------------------------------------
__global__ __launch_bounds__(256) void k_a1(const float* __restrict__ hidden,
                                            const float* __restrict__ W,
                                            const float* __restrict__ bias) {
    int gw   = (blockIdx.x * 256 + threadIdx.x) >> 5;  // global warp = b*Hn + h
    int lane = threadIdx.x & 31;
    int h = gw & (Hn - 1);
    int b = gw >> 10;
    const float* wr = W + (size_t)h * (2 * Hn);
    const float* hr = hidden + (size_t)b * Hn;
    float s = 0.f;
#pragma unroll 4
    for (int k = lane; k < Hn; k += 32) s += wr[k] * hr[k];
#pragma unroll
    for (int o = 16; o; o >>= 1) s += __shfl_xor_sync(0xffffffffu, s, o);
    if (lane == 0) g_A1[gw] = s + bias[h];
}

// ---------------------------------------------------------------------------
// Kernel 2: for each (b, s-tile): loop h-chunks of 128:
//   C[h, s] = sum_k W[h, Hn + k] * enc[b, k, s]   (register-tiled, f32x2 FMA)
//   logit[b,s] += sum_h v[h] * tanhf(A1[b,h] + C[h,s])
// ---------------------------------------------------------------------------
__global__ __launch_bounds__(256, 2) void k_energy(const float* __restrict__ enc,
                                                   const float* __restrict__ W,
                                                   const float* __restrict__ v) {
    __shared__ float sW[TH][KT];   // [h][k]  16 KB
    __shared__ float sE[KT][TS];   // [k][s]  16 KB
    __shared__ float sLogit[TS];

    const int tid = threadIdx.x;
    const int b  = blockIdx.y;
    const int sc = blockIdx.x * TS;
    const int tr = tid >> 4;   // 0..15  -> 8 h-rows each
    const int tc = tid & 15;   // 0..15  -> 8 s-cols each

    for (int i = tid; i < TS; i += 256) sLogit[i] = 0.f;

    const float* encB = enc + (size_t)b * Sn * Hn;

    for (int hc = 0; hc < Hn; hc += TH) {
        unsigned long long acc[8][4];  // [h][s-pair] packed f32x2
#pragma unroll
        for (int i = 0; i < 8; i++)
#pragma unroll
            for (int j = 0; j < 4; j++) acc[i][j] = 0ull;

        for (int kc = 0; kc < Hn; kc += KT) {
            __syncthreads();
            // load W2 tile [TH x KT]: W[hc+row, Hn + kc + k]
#pragma unroll
            for (int t = 0; t < 4; t++) {
                int idx = tid + t * 256;        // float4 units: 128 rows * 8
                int row = idx >> 3, c4 = idx & 7;
                float4 w4 = *(const float4*)(W + (size_t)(hc + row) * (2 * Hn) + Hn + kc + c4 * 4);
                *(float4*)&sW[row][c4 * 4] = w4;
            }
            // load E tile [KT x TS]: enc[b, kc+row, sc + s]  (s contiguous)
#pragma unroll
            for (int t = 0; t < 4; t++) {
                int idx = tid + t * 256;        // float4 units: 32 rows * 32
                int row = idx >> 5, c4 = idx & 31;
                float4 e4 = *(const float4*)(encB + (size_t)(kc + row) * Hn + sc + c4 * 4);
                *(float4*)&sE[row][c4 * 4] = e4;
            }
            __syncthreads();

#pragma unroll
            for (int kk = 0; kk < KT; kk++) {
                unsigned long long e2[4];
                const unsigned long long* ep = (const unsigned long long*)&sE[kk][tc * 8];
                e2[0] = ep[0]; e2[1] = ep[1]; e2[2] = ep[2]; e2[3] = ep[3];
#pragma unroll
                for (int i = 0; i < 8; i++) {
                    unsigned wb = __float_as_uint(sW[tr * 8 + i][kk]);
                    unsigned long long wp;
                    asm("mov.b64 %0, {%1, %1};" : "=l"(wp) : "r"(wb));
#pragma unroll
                    for (int j = 0; j < 4; j++)
                        asm("fma.rn.f32x2 %0, %1, %2, %0;"
                            : "+l"(acc[i][j]) : "l"(wp), "l"(e2[j]));
                }
            }
        }

        // epilogue for this h-chunk: tanh + v-dot, accumulate into sLogit
        float ps[8];
#pragma unroll
        for (int j = 0; j < 8; j++) ps[j] = 0.f;
#pragma unroll
        for (int i = 0; i < 8; i++) {
            int h = hc + tr * 8 + i;
            float a1 = g_A1[b * Hn + h];
            float vv = __ldg(v + h);
#pragma unroll
            for (int j = 0; j < 4; j++) {
                unsigned lo, hi;
                asm("mov.b64 {%0, %1}, %2;" : "=r"(lo), "=r"(hi) : "l"(acc[i][j]));
                ps[2 * j]     += vv * tanhf(a1 + __uint_as_float(lo));
                ps[2 * j + 1] += vv * tanhf(a1 + __uint_as_float(hi));
            }
        }
#pragma unroll
        for (int j = 0; j < 8; j++) atomicAdd(&sLogit[tc * 8 + j], ps[j]);
    }
    __syncthreads();
    if (tid < TS) g_logits[(size_t)b * Sn + sc + tid] = sLogit[tid];
}

// ---------------------------------------------------------------------------
// Kernel 3: softmax over s per batch; writes g_scores (+ d_out scores region)
// ---------------------------------------------------------------------------
__global__ __launch_bounds__(256) void k_softmax(float* __restrict__ scores_out,
                                                 int write_out) {
    __shared__ float red[8];
    int b = blockIdx.x, tid = threadIdx.x;
    int lane = tid & 31, wid = tid >> 5;
    float l[4];
    float m = -1e30f;
#pragma unroll
    for (int t = 0; t < 4; t++) {
        l[t] = g_logits[b * Sn + tid + t * 256];
        m = fmaxf(m, l[t]);
    }
#pragma unroll
    for (int o = 16; o; o >>= 1) m = fmaxf(m, __shfl_xor_sync(0xffffffffu, m, o));
    if (lane == 0) red[wid] = m;
    __syncthreads();
    if (wid == 0) {
        float x = red[lane & 7];
#pragma unroll
        for (int o = 4; o; o >>= 1) x = fmaxf(x, __shfl_xor_sync(0xffffffffu, x, o));
        if (lane == 0) red[0] = x;
    }
    __syncthreads();
    m = red[0];
    float s = 0.f;
#pragma unroll
    for (int t = 0; t < 4; t++) {
        l[t] = __expf(l[t] - m);
        s += l[t];
    }
#pragma unroll
    for (int o = 16; o; o >>= 1) s += __shfl_xor_sync(0xffffffffu, s, o);
    __syncthreads();  // red reuse
    if (lane == 0) red[wid] = s;
    __syncthreads();
    if (wid == 0) {
        float x = red[lane & 7];
#pragma unroll
        for (int o = 4; o; o >>= 1) x += __shfl_xor_sync(0xffffffffu, x, o);
        if (lane == 0) red[0] = x;
    }
    __syncthreads();
    float inv = 1.f / red[0];
#pragma unroll
    for (int t = 0; t < 4; t++) {
        float sv = l[t] * inv;
        g_scores[b * Sn + tid + t * 256] = sv;
        if (write_out) scores_out[b * Sn + tid + t * 256] = sv;
    }
}

// ---------------------------------------------------------------------------
// Kernel 4: context[b,h] = sum_s scores[b,s] * enc[b,s,h]
// grid (Hn/128, Bn), 128 threads, one h-column per thread
// ---------------------------------------------------------------------------
__global__ __launch_bounds__(128) void k_context(const float* __restrict__ enc,
                                                 float* __restrict__ out_ctx) {
    __shared__ float ssc[Sn];
    int b = blockIdx.y;
    int hc = blockIdx.x * 128;
    int tid = threadIdx.x;
    for (int i = tid; i < Sn; i += 128) ssc[i] = g_scores[b * Sn + i];
    __syncthreads();
    const float* e = enc + (size_t)b * Sn * Hn + hc + tid;
    float a0 = 0.f, a1 = 0.f, a2 = 0.f, a3 = 0.f;
#pragma unroll 2
    for (int s = 0; s < Sn; s += 4) {
        a0 += ssc[s]     * e[(size_t)s * Hn];
        a1 += ssc[s + 1] * e[(size_t)(s + 1) * Hn];
        a2 += ssc[s + 2] * e[(size_t)(s + 2) * Hn];
        a3 += ssc[s + 3] * e[(size_t)(s + 3) * Hn];
    }
    out_ctx[b * Hn + hc + tid] = (a0 + a1) + (a2 + a3);
}

// ---------------------------------------------------------------------------
extern "C" void kernel_launch(void* const* d_in, const int* in_sizes, int n_in,
                              void* d_out, int out_size) {
    const float* hidden = (const float*)d_in[0];
    const float* enc    = (const float*)d_in[1];
    const float* W      = (const float*)d_in[2];
    const float* bias   = (const float*)d_in[3];
    const float* v      = (const float*)d_in[4];

    float* out = (float*)d_out;
    float* ctx = out;                 // context: [B, H]
    float* scr = out + Bn * Hn;       // scores:  [B, 1, S]
    int write_scores = (out_size >= Bn * Hn + Bn * Sn) ? 1 : 0;

    k_a1<<<(Bn * Hn) / 8, 256>>>(hidden, W, bias);

    dim3 g2(Sn / TS, Bn);
    k_energy<<<g2, 256>>>(enc, W, v);

    k_softmax<<<Bn, 256>>>(scr, write_scores);

    dim3 g4(Hn / 128, Bn);
    k_context<<<g4, 128>>>(enc, ctx);
}

// round 5
// speedup vs baseline: 5.7422x; 5.7422x over previous
#include <cuda_runtime.h>
#include <cuda_bf16.h>
#include <stdint.h>
#include <math.h>

#define Bn 32
#define Hn 1024
#define Sn 1024

// ---------------- scratch (device globals; no allocation allowed) ----------
__device__ float g_A1[Bn * Hn];
__device__ float g_logits[Bn * Sn];
__device__ float g_scores[Bn * Sn];
__device__ __nv_bfloat16 g_W2bf[Hn * Hn];         // [h][k]  K-major
__device__ __nv_bfloat16 g_encT[Bn * Sn * Hn];    // [b][s][k] = enc[b][k][s]

// ---------------- helpers ---------------------------------------------------
__device__ __forceinline__ uint32_t smem_u32(const void* p) {
    uint32_t a;
    asm("{ .reg .u64 t; cvta.to.shared.u64 t, %1; cvt.u32.u64 %0, t; }" : "=r"(a) : "l"(p));
    return a;
}
__device__ __forceinline__ float fast_tanh(float x) {
    float y;
    asm("tanh.approx.f32 %0, %1;" : "=f"(y) : "f"(x));
    return y;
}
#define CP_ASYNC16(smem_a, gptr) \
    asm volatile("cp.async.cg.shared.global [%0], [%1], 16;" :: "r"(smem_a), "l"(gptr) : "memory")

#define LDSM_X4(r, addr) \
    asm volatile("ldmatrix.sync.aligned.m8n8.x4.shared.b16 {%0,%1,%2,%3}, [%4];" \
        : "=r"((r)[0]), "=r"((r)[1]), "=r"((r)[2]), "=r"((r)[3]) : "r"(addr))

#define MMA16816(d, a, b0, b1) \
    asm volatile("mma.sync.aligned.m16n8k16.row.col.f32.bf16.bf16.f32 " \
        "{%0,%1,%2,%3}, {%4,%5,%6,%7}, {%8,%9}, {%0,%1,%2,%3};" \
        : "+f"((d)[0]), "+f"((d)[1]), "+f"((d)[2]), "+f"((d)[3]) \
        : "r"((a)[0]), "r"((a)[1]), "r"((a)[2]), "r"((a)[3]), "r"(b0), "r"(b1))

// SMEM layout for k_energy (dynamic):
//   [0,512)       sLog (128 floats)
//   [1024, +18432)         A stage0 (128 rows x 72 bf16, 144B stride)
//   [19456, +18432)        B stage0
//   [37888, +18432)        A stage1
//   [56320, +18432)        B stage1
#define STAGE_BYTES 36864
#define A_OFF(s) (1024 + (s) * STAGE_BYTES)
#define B_OFF(s) (1024 + (s) * STAGE_BYTES + 18432)
#define SMEM_BYTES (1024 + 2 * STAGE_BYTES)   // 74752
#define LDB 144                                // row stride bytes (72 bf16)

// ---------------------------------------------------------------------------
// Prep: W2 -> bf16 K-major; also zero g_logits
// ---------------------------------------------------------------------------
__global__ __launch_bounds__(256) void k_prep_w2(const float* __restrict__ W) {
    int row = blockIdx.x, tid = threadIdx.x;
    const float4* src = (const float4*)(W + (size_t)row * (2 * Hn) + Hn);
    float4 f = src[tid];
    __nv_bfloat162* dst = (__nv_bfloat162*)(g_W2bf + (size_t)row * Hn);
    dst[2 * tid]     = __floats2bfloat162_rn(f.x, f.y);
    dst[2 * tid + 1] = __floats2bfloat162_rn(f.z, f.w);
    int gi = blockIdx.x * 256 + tid;
    if (gi < Bn * Sn) g_logits[gi] = 0.f;
}

// ---------------------------------------------------------------------------
// Prep: encT[b][s][k] = bf16(enc[b][k][s])  (tiled 32x32 transpose)
// ---------------------------------------------------------------------------
__global__ __launch_bounds__(256) void k_prep_enc(const float* __restrict__ enc) {
    __shared__ float t[32][33];
    int b = blockIdx.z, k0 = blockIdx.y * 32, s0 = blockIdx.x * 32;
    int tx = threadIdx.x, ty = threadIdx.y;
    const float* src = enc + ((size_t)b * Sn + k0) * Hn + s0;
#pragma unroll
    for (int r = ty; r < 32; r += 8) t[r][tx] = src[(size_t)r * Hn + tx];
    __syncthreads();
    __nv_bfloat16* dst = g_encT + ((size_t)b * Sn + s0) * Hn + k0;
#pragma unroll
    for (int r = ty; r < 32; r += 8)
        dst[(size_t)r * Hn + tx] = __float2bfloat16(t[tx][r]);
}

// ---------------------------------------------------------------------------
// A1[b,h] = bias[h] + sum_k hidden[b,k] * W[h,k]  (one warp per output)
// ---------------------------------------------------------------------------
__global__ __launch_bounds__(256) void k_a1(const float* __restrict__ hidden,
                                            const float* __restrict__ W,
                                            const float* __restrict__ bias) {
    int gw = (blockIdx.x * 256 + threadIdx.x) >> 5;
    int lane = threadIdx.x & 31;
    int h = gw & (Hn - 1);
    int b = gw >> 10;
    const float* wr = W + (size_t)h * (2 * Hn);
    const float* hr = hidden + (size_t)b * Hn;
    float s = 0.f;
#pragma unroll 4
    for (int k = lane; k < Hn; k += 32) s += wr[k] * hr[k];
#pragma unroll
    for (int o = 16; o; o >>= 1) s += __shfl_xor_sync(0xffffffffu, s, o);
    if (lane == 0) g_A1[gw] = s + bias[h];
}

// ---------------------------------------------------------------------------
// chunk loader: A[128 x 64] from W2bf, B[128 x 64] from encT (bf16, cp.async)
// ---------------------------------------------------------------------------
__device__ __forceinline__ void load_chunk(int tid,
                                           const __nv_bfloat16* gW,
                                           const __nv_bfloat16* gE,
                                           int kc, uint32_t aBase, uint32_t bBase) {
#pragma unroll
    for (int t = 0; t < 4; t++) {
        int idx = tid + t * 256;
        int r = idx >> 3, c = idx & 7;
        CP_ASYNC16(aBase + r * LDB + c * 16, gW + (size_t)r * Hn + kc + c * 8);
    }
#pragma unroll
    for (int t = 0; t < 4; t++) {
        int idx = tid + t * 256;
        int r = idx >> 3, c = idx & 7;
        CP_ASYNC16(bBase + r * LDB + c * 16, gE + (size_t)r * Hn + kc + c * 8);
    }
    asm volatile("cp.async.commit_group;" ::: "memory");
}

// ---------------------------------------------------------------------------
// k_energy: one CTA per (b, h-tile=128, s-tile=128).
// D[h,s] = sum_k W2bf[h,k] * encT[b,s,k]  via mma.sync m16n8k16 bf16 (HMMA).
// Epilogue: logits[b,s] += sum_h v[h] * tanh(A1[b,h] + D[h,s])
// ---------------------------------------------------------------------------
__global__ __launch_bounds__(256, 2) void k_energy(const float* __restrict__ v) {
    extern __shared__ char smem[];
    uint32_t sb = smem_u32(smem);
    float* sLog = (float*)smem;

    const int tid = threadIdx.x;
    const int l   = tid & 31;
    const int w   = tid >> 5;
    const int wr  = w >> 1;     // 0..3 : h-subtile (32 rows)
    const int wc  = w & 1;      // 0..1 : s-subtile (64 cols)
    const int b   = blockIdx.z;
    const int hc  = blockIdx.y * 128;
    const int sc  = blockIdx.x * 128;

    if (tid < 128) sLog[tid] = 0.f;

    const __nv_bfloat16* gW = g_W2bf + (size_t)hc * Hn;
    const __nv_bfloat16* gE = g_encT + ((size_t)b * Sn + sc) * Hn;

    float acc[2][8][4];
#pragma unroll
    for (int mi = 0; mi < 2; mi++)
#pragma unroll
        for (int ni = 0; ni < 8; ni++)
#pragma unroll
            for (int j = 0; j < 4; j++) acc[mi][ni][j] = 0.f;

    // ldmatrix lane addressing (constant per thread)
    const int a_row  = l & 15;          // m row within 16
    const int a_kh   = (l >> 4) * 8;    // k half
    const int b_nr   = (l & 7) | ((l >> 4) << 3);  // n row within 16
    const int b_kh   = ((l >> 3) & 1) * 8;

    load_chunk(tid, gW, gE, 0, sb + A_OFF(0), sb + B_OFF(0));

    for (int i = 0; i < 16; i++) {
        int p = i & 1;
        if (i + 1 < 16) {
            load_chunk(tid, gW, gE, (i + 1) * 64, sb + A_OFF(p ^ 1), sb + B_OFF(p ^ 1));
            asm volatile("cp.async.wait_group 1;" ::: "memory");
        } else {
            asm volatile("cp.async.wait_group 0;" ::: "memory");
        }
        __syncthreads();

        uint32_t aT = sb + A_OFF(p);
        uint32_t bT = sb + B_OFF(p);
#pragma unroll
        for (int k16 = 0; k16 < 4; k16++) {
            uint32_t ar[2][4], br[4][4];
            int kb = (k16 * 16) * 2;   // byte offset of k16 within row
#pragma unroll
            for (int mi = 0; mi < 2; mi++)
                LDSM_X4(ar[mi], aT + (uint32_t)((wr * 32 + mi * 16 + a_row) * LDB) + kb + a_kh * 2);
#pragma unroll
            for (int g = 0; g < 4; g++)
                LDSM_X4(br[g], bT + (uint32_t)((wc * 64 + g * 16 + b_nr) * LDB) + kb + b_kh * 2);
#pragma unroll
            for (int mi = 0; mi < 2; mi++)
#pragma unroll
                for (int ni = 0; ni < 8; ni++)
                    MMA16816(acc[mi][ni], ar[mi], br[ni >> 1][(ni & 1) * 2],
                             br[ni >> 1][(ni & 1) * 2 + 1]);
        }
        __syncthreads();
    }

    // ---- epilogue: tanh + v-dot, reduce over h ----
    float a1v[2][2], vv[2][2];
#pragma unroll
    for (int mi = 0; mi < 2; mi++)
#pragma unroll
        for (int j = 0; j < 2; j++) {
            int h = hc + wr * 32 + mi * 16 + (l >> 2) + j * 8;
            a1v[mi][j] = g_A1[b * Hn + h];
            vv[mi][j]  = v[h];
        }

    float part[8][2];
#pragma unroll
    for (int ni = 0; ni < 8; ni++) { part[ni][0] = 0.f; part[ni][1] = 0.f; }
#pragma unroll
    for (int mi = 0; mi < 2; mi++)
#pragma unroll
        for (int ni = 0; ni < 8; ni++) {
            part[ni][0] += vv[mi][0] * fast_tanh(a1v[mi][0] + acc[mi][ni][0]);
            part[ni][1] += vv[mi][0] * fast_tanh(a1v[mi][0] + acc[mi][ni][1]);
            part[ni][0] += vv[mi][1] * fast_tanh(a1v[mi][1] + acc[mi][ni][2]);
            part[ni][1] += vv[mi][1] * fast_tanh(a1v[mi][1] + acc[mi][ni][3]);
        }
#pragma unroll
    for (int ni = 0; ni < 8; ni++)
#pragma unroll
        for (int e = 0; e < 2; e++) {
            float s = part[ni][e];
            s += __shfl_xor_sync(0xffffffffu, s, 4);
            s += __shfl_xor_sync(0xffffffffu, s, 8);
            s += __shfl_xor_sync(0xffffffffu, s, 16);
            if (l < 4) atomicAdd(&sLog[wc * 64 + ni * 8 + (l & 3) * 2 + e], s);
        }
    __syncthreads();
    if (tid < 128) atomicAdd(&g_logits[b * Sn + sc + tid], sLog[tid]);
}

// ---------------------------------------------------------------------------
// softmax over s per batch; writes scores output; zeros ctx for k_context
// ---------------------------------------------------------------------------
__global__ __launch_bounds__(256) void k_softmax(float* __restrict__ scores_out,
                                                 int write_out,
                                                 float* __restrict__ ctx) {
    __shared__ float red[8];
    int b = blockIdx.x, tid = threadIdx.x;
    int lane = tid & 31, wid = tid >> 5;
#pragma unroll
    for (int t = 0; t < 4; t++) ctx[b * Hn + tid + t * 256] = 0.f;
    float l[4];
    float m = -1e30f;
#pragma unroll
    for (int t = 0; t < 4; t++) {
        l[t] = g_logits[b * Sn + tid + t * 256];
        m = fmaxf(m, l[t]);
    }
#pragma unroll
    for (int o = 16; o; o >>= 1) m = fmaxf(m, __shfl_xor_sync(0xffffffffu, m, o));
    if (lane == 0) red[wid] = m;
    __syncthreads();
    if (wid == 0) {
        float x = red[lane & 7];
#pragma unroll
        for (int o = 4; o; o >>= 1) x = fmaxf(x, __shfl_xor_sync(0xffffffffu, x, o));
        if (lane == 0) red[0] = x;
    }
    __syncthreads();
    m = red[0];
    float s = 0.f;
#pragma unroll
    for (int t = 0; t < 4; t++) {
        l[t] = __expf(l[t] - m);
        s += l[t];
    }
#pragma unroll
    for (int o = 16; o; o >>= 1) s += __shfl_xor_sync(0xffffffffu, s, o);
    __syncthreads();
    if (lane == 0) red[wid] = s;
    __syncthreads();
    if (wid == 0) {
        float x = red[lane & 7];
#pragma unroll
        for (int o = 4; o; o >>= 1) x += __shfl_xor_sync(0xffffffffu, x, o);
        if (lane == 0) red[0] = x;
    }
    __syncthreads();
    float inv = 1.f / red[0];
#pragma unroll
    for (int t = 0; t < 4; t++) {
        float sv = l[t] * inv;
        g_scores[b * Sn + tid + t * 256] = sv;
        if (write_out) scores_out[b * Sn + tid + t * 256] = sv;
    }
}

// ---------------------------------------------------------------------------
// context[b,h] = sum_s scores[b,s] * enc[b,s,h]; s split 4 ways, atomicAdd
// ---------------------------------------------------------------------------
__global__ __launch_bounds__(128) void k_context(const float* __restrict__ enc,
                                                 float* __restrict__ out_ctx) {
    __shared__ float ssc[256];
    int hc = blockIdx.x * 128;
    int b  = blockIdx.y;
    int s0 = blockIdx.z * 256;
    int tid = threadIdx.x;
    ssc[tid]       = g_scores[b * Sn + s0 + tid];
    ssc[tid + 128] = g_scores[b * Sn + s0 + tid + 128];
    __syncthreads();
    const float* e = enc + ((size_t)b * Sn + s0) * Hn + hc + tid;
    float a0 = 0.f, a1 = 0.f, a2 = 0.f, a3 = 0.f;
#pragma unroll 2
    for (int s = 0; s < 256; s += 4) {
        a0 += ssc[s]     * e[(size_t)s * Hn];
        a1 += ssc[s + 1] * e[(size_t)(s + 1) * Hn];
        a2 += ssc[s + 2] * e[(size_t)(s + 2) * Hn];
        a3 += ssc[s + 3] * e[(size_t)(s + 3) * Hn];
    }
    atomicAdd(&out_ctx[b * Hn + hc + tid], (a0 + a1) + (a2 + a3));
}

// ---------------------------------------------------------------------------
extern "C" void kernel_launch(void* const* d_in, const int* in_sizes, int n_in,
                              void* d_out, int out_size) {
    const float* hidden = (const float*)d_in[0];
    const float* enc    = (const float*)d_in[1];
    const float* W      = (const float*)d_in[2];
    const float* bias   = (const float*)d_in[3];
    const float* v      = (const float*)d_in[4];

    float* out = (float*)d_out;
    float* ctx = out;                 // context: [B, H]
    float* scr = out + Bn * Hn;       // scores:  [B, 1, S]
    int write_scores = (out_size >= Bn * Hn + Bn * Sn) ? 1 : 0;

    cudaFuncSetAttribute(k_energy, cudaFuncAttributeMaxDynamicSharedMemorySize, SMEM_BYTES);

    k_prep_w2<<<1024, 256>>>(W);
    k_prep_enc<<<dim3(32, 32, 32), dim3(32, 8)>>>(enc);
    k_a1<<<(Bn * Hn) / 8, 256>>>(hidden, W, bias);

    k_energy<<<dim3(8, 8, 32), 256, SMEM_BYTES>>>(v);

    k_softmax<<<Bn, 256>>>(scr, write_scores, ctx);
    k_context<<<dim3(8, 32, 4), 128>>>(enc, ctx);
}

// round 6
// speedup vs baseline: 5.8522x; 1.0191x over previous
#include <cuda_runtime.h>
#include <cuda_bf16.h>
#include <stdint.h>
#include <math.h>

#define Bn 32
#define Hn 1024
#define Sn 1024

// ---------------- scratch (device globals; no allocation allowed) ----------
__device__ float g_A1[Bn * Hn];
__device__ float g_logits[Bn * Sn];
__device__ float g_scores[Bn * Sn];
__device__ __nv_bfloat16 g_W2bf[Hn * Hn];         // [h][k]  K-major
__device__ __nv_bfloat16 g_encT[Bn * Sn * Hn];    // [b][s][k] = enc[b][k][s]

// ---------------- helpers ---------------------------------------------------
__device__ __forceinline__ uint32_t smem_u32(const void* p) {
    uint32_t a;
    asm("{ .reg .u64 t; cvta.to.shared.u64 t, %1; cvt.u32.u64 %0, t; }" : "=r"(a) : "l"(p));
    return a;
}
__device__ __forceinline__ float fast_tanh(float x) {
    float y;
    asm("tanh.approx.f32 %0, %1;" : "=f"(y) : "f"(x));
    return y;
}
#define CP_ASYNC16(smem_a, gptr) \
    asm volatile("cp.async.cg.shared.global [%0], [%1], 16;" :: "r"(smem_a), "l"(gptr) : "memory")

#define LDSM_X4(r, addr) \
    asm volatile("ldmatrix.sync.aligned.m8n8.x4.shared.b16 {%0,%1,%2,%3}, [%4];" \
        : "=r"((r)[0]), "=r"((r)[1]), "=r"((r)[2]), "=r"((r)[3]) : "r"(addr))

#define MMA16816(d, a, b0, b1) \
    asm volatile("mma.sync.aligned.m16n8k16.row.col.f32.bf16.bf16.f32 " \
        "{%0,%1,%2,%3}, {%4,%5,%6,%7}, {%8,%9}, {%0,%1,%2,%3};" \
        : "+f"((d)[0]), "+f"((d)[1]), "+f"((d)[2]), "+f"((d)[3]) \
        : "r"((a)[0]), "r"((a)[1]), "r"((a)[2]), "r"((a)[3]), "r"(b0), "r"(b1))

// SMEM layout for k_energy: 4-stage pipeline, K-chunk = 32
//   [0,512)    sLog (128 floats)
//   stages at 1024 + s*20480 : A[128 x 80B] then B[128 x 80B]
#define KCH 32
#define LDB 80                           // 32 bf16 = 64B + 16B pad
#define STAGE_BYTES 20480
#define A_OFF(s) (1024 + (s) * STAGE_BYTES)
#define B_OFF(s) (1024 + (s) * STAGE_BYTES + 10240)
#define SMEM_BYTES (1024 + 4 * STAGE_BYTES)   // 82944

// ---------------------------------------------------------------------------
// Prep: W2 -> bf16 K-major; also zero g_logits
// ---------------------------------------------------------------------------
__global__ __launch_bounds__(256) void k_prep_w2(const float* __restrict__ W) {
    int row = blockIdx.x, tid = threadIdx.x;
    const float4* src = (const float4*)(W + (size_t)row * (2 * Hn) + Hn);
    float4 f = src[tid];
    __nv_bfloat162* dst = (__nv_bfloat162*)(g_W2bf + (size_t)row * Hn);
    dst[2 * tid]     = __floats2bfloat162_rn(f.x, f.y);
    dst[2 * tid + 1] = __floats2bfloat162_rn(f.z, f.w);
    int gi = blockIdx.x * 256 + tid;
    if (gi < Bn * Sn) g_logits[gi] = 0.f;
}

// ---------------------------------------------------------------------------
// Prep: encT[b][s][k] = bf16(enc[b][k][s])  (64x64 tiles, vectorized)
// ---------------------------------------------------------------------------
__global__ __launch_bounds__(256) void k_prep_enc(const float* __restrict__ enc) {
    __shared__ float t[64 * 67];                 // [k][s], stride 67
    int b = blockIdx.z, k0 = blockIdx.y * 64, s0 = blockIdx.x * 64;
    int tid = threadIdx.x;
    const float* src = enc + ((size_t)b * Sn + k0) * Hn + s0;
#pragma unroll
    for (int it = 0; it < 4; it++) {
        int i = tid + it * 256;                  // 1024 float4 slots
        int r = i >> 4, c = i & 15;
        float4 f = *(const float4*)(src + (size_t)r * Hn + c * 4);
        float* tp = &t[r * 67 + c * 4];
        tp[0] = f.x; tp[1] = f.y; tp[2] = f.z; tp[3] = f.w;
    }
    __syncthreads();
    __nv_bfloat16* dst = g_encT + ((size_t)b * Sn + s0) * Hn + k0;
#pragma unroll
    for (int it = 0; it < 8; it++) {
        int i = tid + it * 256;                  // 2048 bf162 slots
        int srow = i >> 5, p = i & 31;
        __nv_bfloat162 v = __floats2bfloat162_rn(t[(2 * p) * 67 + srow],
                                                 t[(2 * p + 1) * 67 + srow]);
        *(__nv_bfloat162*)(dst + (size_t)srow * Hn + 2 * p) = v;
    }
}

// ---------------------------------------------------------------------------
// A1[b,h] = bias[h] + sum_k hidden[b,k] * W[h,k]  (one warp per output)
// ---------------------------------------------------------------------------
__global__ __launch_bounds__(256) void k_a1(const float* __restrict__ hidden,
                                            const float* __restrict__ W,
                                            const float* __restrict__ bias) {
    int gw = (blockIdx.x * 256 + threadIdx.x) >> 5;
    int lane = threadIdx.x & 31;
    int h = gw & (Hn - 1);
    int b = gw >> 10;
    const float* wr = W + (size_t)h * (2 * Hn);
    const float* hr = hidden + (size_t)b * Hn;
    float s = 0.f;
#pragma unroll 4
    for (int k = lane; k < Hn; k += 32) s += wr[k] * hr[k];
#pragma unroll
    for (int o = 16; o; o >>= 1) s += __shfl_xor_sync(0xffffffffu, s, o);
    if (lane == 0) g_A1[gw] = s + bias[h];
}

// ---------------------------------------------------------------------------
// chunk loader: A[128 x 32] W2bf, B[128 x 32] encT (bf16, cp.async, K=32)
// ---------------------------------------------------------------------------
__device__ __forceinline__ void load_chunk(int tid,
                                           const __nv_bfloat16* gW,
                                           const __nv_bfloat16* gE,
                                           int kc, uint32_t aBase, uint32_t bBase) {
#pragma unroll
    for (int t = 0; t < 2; t++) {
        int idx = tid + t * 256;                 // 512 x 16B for A
        int r = idx >> 2, c = idx & 3;
        CP_ASYNC16(aBase + r * LDB + c * 16, gW + (size_t)r * Hn + kc + c * 8);
    }
#pragma unroll
    for (int t = 0; t < 2; t++) {
        int idx = tid + t * 256;                 // 512 x 16B for B
        int r = idx >> 2, c = idx & 3;
        CP_ASYNC16(bBase + r * LDB + c * 16, gE + (size_t)r * Hn + kc + c * 8);
    }
    asm volatile("cp.async.commit_group;" ::: "memory");
}

// ---------------------------------------------------------------------------
// k_energy: one CTA per (b, h-tile=128, s-tile=128).
// D[h,s] = sum_k W2bf[h,k] * encT[b,s,k]  via mma.sync m16n8k16 bf16 (HMMA).
// 4-stage cp.async pipeline, prefetch distance 3, one barrier per K-chunk.
// Epilogue: logits[b,s] += sum_h v[h] * tanh(A1[b,h] + D[h,s])
// ---------------------------------------------------------------------------
__global__ __launch_bounds__(256, 2) void k_energy(const float* __restrict__ v) {
    extern __shared__ char smem[];
    uint32_t sb = smem_u32(smem);
    float* sLog = (float*)smem;

    const int tid = threadIdx.x;
    const int l   = tid & 31;
    const int w   = tid >> 5;
    const int wr  = w >> 1;     // 0..3 : h-subtile (32 rows)
    const int wc  = w & 1;      // 0..1 : s-subtile (64 cols)
    const int b   = blockIdx.z;
    const int hc  = blockIdx.y * 128;
    const int sc  = blockIdx.x * 128;

    if (tid < 128) sLog[tid] = 0.f;

    const __nv_bfloat16* gW = g_W2bf + (size_t)hc * Hn;
    const __nv_bfloat16* gE = g_encT + ((size_t)b * Sn + sc) * Hn;

    float acc[2][8][4];
#pragma unroll
    for (int mi = 0; mi < 2; mi++)
#pragma unroll
        for (int ni = 0; ni < 8; ni++)
#pragma unroll
            for (int j = 0; j < 4; j++) acc[mi][ni][j] = 0.f;

    // ldmatrix lane addressing (constant per thread)
    const int a_row = l & 15;
    const int a_kb  = (l >> 4) * 16;                    // k-half byte offset
    const int b_nr  = (l & 7) | ((l >> 4) << 3);
    const int b_kb  = ((l >> 3) & 1) * 16;

    // preload stages 0..2
    load_chunk(tid, gW, gE, 0 * KCH, sb + A_OFF(0), sb + B_OFF(0));
    load_chunk(tid, gW, gE, 1 * KCH, sb + A_OFF(1), sb + B_OFF(1));
    load_chunk(tid, gW, gE, 2 * KCH, sb + A_OFF(2), sb + B_OFF(2));

    for (int i = 0; i < 32; i++) {
        __syncthreads();                         // all warps done with stage (i+3)&3
        if (i + 3 < 32) {
            load_chunk(tid, gW, gE, (i + 3) * KCH,
                       sb + A_OFF((i + 3) & 3), sb + B_OFF((i + 3) & 3));
            asm volatile("cp.async.wait_group 3;" ::: "memory");
        } else {
            asm volatile("cp.async.wait_group 0;" ::: "memory");
        }

        uint32_t aT = sb + A_OFF(i & 3);
        uint32_t bT = sb + B_OFF(i & 3);
#pragma unroll
        for (int k16 = 0; k16 < 2; k16++) {
            uint32_t ar[2][4], br[4][4];
            int kb = k16 * 32;
#pragma unroll
            for (int mi = 0; mi < 2; mi++)
                LDSM_X4(ar[mi], aT + (uint32_t)((wr * 32 + mi * 16 + a_row) * LDB) + kb + a_kb);
#pragma unroll
            for (int g = 0; g < 4; g++)
                LDSM_X4(br[g], bT + (uint32_t)((wc * 64 + g * 16 + b_nr) * LDB) + kb + b_kb);
#pragma unroll
            for (int mi = 0; mi < 2; mi++)
#pragma unroll
                for (int ni = 0; ni < 8; ni++)
                    MMA16816(acc[mi][ni], ar[mi], br[ni >> 1][(ni & 1) * 2],
                             br[ni >> 1][(ni & 1) * 2 + 1]);
        }
    }

    // ---- epilogue: tanh + v-dot, reduce over h ----
    float a1v[2][2], vv[2][2];
#pragma unroll
    for (int mi = 0; mi < 2; mi++)
#pragma unroll
        for (int j = 0; j < 2; j++) {
            int h = hc + wr * 32 + mi * 16 + (l >> 2) + j * 8;
            a1v[mi][j] = g_A1[b * Hn + h];
            vv[mi][j]  = v[h];
        }

    float part[8][2];
#pragma unroll
    for (int ni = 0; ni < 8; ni++) { part[ni][0] = 0.f; part[ni][1] = 0.f; }
#pragma unroll
    for (int mi = 0; mi < 2; mi++)
#pragma unroll
        for (int ni = 0; ni < 8; ni++) {
            part[ni][0] += vv[mi][0] * fast_tanh(a1v[mi][0] + acc[mi][ni][0]);
            part[ni][1] += vv[mi][0] * fast_tanh(a1v[mi][0] + acc[mi][ni][1]);
            part[ni][0] += vv[mi][1] * fast_tanh(a1v[mi][1] + acc[mi][ni][2]);
            part[ni][1] += vv[mi][1] * fast_tanh(a1v[mi][1] + acc[mi][ni][3]);
        }
#pragma unroll
    for (int ni = 0; ni < 8; ni++)
#pragma unroll
        for (int e = 0; e < 2; e++) {
            float s = part[ni][e];
            s += __shfl_xor_sync(0xffffffffu, s, 4);
            s += __shfl_xor_sync(0xffffffffu, s, 8);
            s += __shfl_xor_sync(0xffffffffu, s, 16);
            if (l < 4) atomicAdd(&sLog[wc * 64 + ni * 8 + (l & 3) * 2 + e], s);
        }
    __syncthreads();
    if (tid < 128) atomicAdd(&g_logits[b * Sn + sc + tid], sLog[tid]);
}

// ---------------------------------------------------------------------------
// softmax over s per batch; writes scores output; zeros ctx for k_context
// ---------------------------------------------------------------------------
__global__ __launch_bounds__(256) void k_softmax(float* __restrict__ scores_out,
                                                 int write_out,
                                                 float* __restrict__ ctx) {
    __shared__ float red[8];
    int b = blockIdx.x, tid = threadIdx.x;
    int lane = tid & 31, wid = tid >> 5;
#pragma unroll
    for (int t = 0; t < 4; t++) ctx[b * Hn + tid + t * 256] = 0.f;
    float l[4];
    float m = -1e30f;
#pragma unroll
    for (int t = 0; t < 4; t++) {
        l[t] = g_logits[b * Sn + tid + t * 256];
        m = fmaxf(m, l[t]);
    }
#pragma unroll
    for (int o = 16; o; o >>= 1) m = fmaxf(m, __shfl_xor_sync(0xffffffffu, m, o));
    if (lane == 0) red[wid] = m;
    __syncthreads();
    if (wid == 0) {
        float x = red[lane & 7];
#pragma unroll
        for (int o = 4; o; o >>= 1) x = fmaxf(x, __shfl_xor_sync(0xffffffffu, x, o));
        if (lane == 0) red[0] = x;
    }
    __syncthreads();
    m = red[0];
    float s = 0.f;
#pragma unroll
    for (int t = 0; t < 4; t++) {
        l[t] = __expf(l[t] - m);
        s += l[t];
    }
#pragma unroll
    for (int o = 16; o; o >>= 1) s += __shfl_xor_sync(0xffffffffu, s, o);
    __syncthreads();
    if (lane == 0) red[wid] = s;
    __syncthreads();
    if (wid == 0) {
        float x = red[lane & 7];
#pragma unroll
        for (int o = 4; o; o >>= 1) x += __shfl_xor_sync(0xffffffffu, x, o);
        if (lane == 0) red[0] = x;
    }
    __syncthreads();
    float inv = 1.f / red[0];
#pragma unroll
    for (int t = 0; t < 4; t++) {
        float sv = l[t] * inv;
        g_scores[b * Sn + tid + t * 256] = sv;
        if (write_out) scores_out[b * Sn + tid + t * 256] = sv;
    }
}

// ---------------------------------------------------------------------------
// context[b,h] = sum_s scores[b,s] * enc[b,s,h]; s split 8 ways, atomicAdd
// ---------------------------------------------------------------------------
__global__ __launch_bounds__(256) void k_context(const float* __restrict__ enc,
                                                 float* __restrict__ out_ctx) {
    __shared__ float ssc[128];
    int hc = blockIdx.x * 256;
    int b  = blockIdx.y;
    int s0 = blockIdx.z * 128;
    int tid = threadIdx.x;
    if (tid < 128) ssc[tid] = g_scores[b * Sn + s0 + tid];
    __syncthreads();
    const float* e = enc + ((size_t)b * Sn + s0) * Hn + hc + tid;
    float a0 = 0.f, a1 = 0.f, a2 = 0.f, a3 = 0.f;
#pragma unroll 4
    for (int s = 0; s < 128; s += 4) {
        a0 += ssc[s]     * e[(size_t)s * Hn];
        a1 += ssc[s + 1] * e[(size_t)(s + 1) * Hn];
        a2 += ssc[s + 2] * e[(size_t)(s + 2) * Hn];
        a3 += ssc[s + 3] * e[(size_t)(s + 3) * Hn];
    }
    atomicAdd(&out_ctx[b * Hn + hc + tid], (a0 + a1) + (a2 + a3));
}

// ---------------------------------------------------------------------------
extern "C" void kernel_launch(void* const* d_in, const int* in_sizes, int n_in,
                              void* d_out, int out_size) {
    const float* hidden = (const float*)d_in[0];
    const float* enc    = (const float*)d_in[1];
    const float* W      = (const float*)d_in[2];
    const float* bias   = (const float*)d_in[3];
    const float* v      = (const float*)d_in[4];

    float* out = (float*)d_out;
    float* ctx = out;                 // context: [B, H]
    float* scr = out + Bn * Hn;       // scores:  [B, 1, S]
    int write_scores = (out_size >= Bn * Hn + Bn * Sn) ? 1 : 0;

    cudaFuncSetAttribute(k_energy, cudaFuncAttributeMaxDynamicSharedMemorySize, SMEM_BYTES);

    k_prep_w2<<<1024, 256>>>(W);
    k_prep_enc<<<dim3(16, 16, 32), 256>>>(enc);
    k_a1<<<(Bn * Hn) / 8, 256>>>(hidden, W, bias);

    k_energy<<<dim3(8, 8, 32), 256, SMEM_BYTES>>>(v);

    k_softmax<<<Bn, 256>>>(scr, write_scores, ctx);
    k_context<<<dim3(4, 32, 8), 256>>>(enc, ctx);
}

// round 7
// speedup vs baseline: 6.3897x; 1.0918x over previous
#include <cuda_runtime.h>
#include <cuda_bf16.h>
#include <stdint.h>
#include <math.h>

#define Bn 32
#define Hn 1024
#define Sn 1024

// ---------------- scratch (device globals; no allocation allowed) ----------
__device__ float g_A1[Bn * Hn];
__device__ float g_logits[Bn * Sn];
__device__ float g_scores[Bn * Sn];
__device__ __nv_bfloat16 g_W2bf[Hn * Hn];         // [h][k]  K-major
__device__ __nv_bfloat16 g_encT[Bn * Sn * Hn];    // [b][s][k] = enc[b][k][s]

// ---------------- helpers ---------------------------------------------------
__device__ __forceinline__ uint32_t smem_u32(const void* p) {
    uint32_t a;
    asm("{ .reg .u64 t; cvta.to.shared.u64 t, %1; cvt.u32.u64 %0, t; }" : "=r"(a) : "l"(p));
    return a;
}
__device__ __forceinline__ float fast_tanh(float x) {
    float y;
    asm("tanh.approx.f32 %0, %1;" : "=f"(y) : "f"(x));
    return y;
}
#define CP_ASYNC16(smem_a, gptr) \
    asm volatile("cp.async.cg.shared.global [%0], [%1], 16;" :: "r"(smem_a), "l"(gptr) : "memory")

#define LDSM_X4(r, addr) \
    asm volatile("ldmatrix.sync.aligned.m8n8.x4.shared.b16 {%0,%1,%2,%3}, [%4];" \
        : "=r"((r)[0]), "=r"((r)[1]), "=r"((r)[2]), "=r"((r)[3]) : "r"(addr))

#define MMA16816(d, a, b0, b1) \
    asm volatile("mma.sync.aligned.m16n8k16.row.col.f32.bf16.bf16.f32 " \
        "{%0,%1,%2,%3}, {%4,%5,%6,%7}, {%8,%9}, {%0,%1,%2,%3};" \
        : "+f"((d)[0]), "+f"((d)[1]), "+f"((d)[2]), "+f"((d)[3]) \
        : "r"((a)[0]), "r"((a)[1]), "r"((a)[2]), "r"((a)[3]), "r"(b0), "r"(b1))

// SMEM layout for k_energy: 2-stage pipeline, K-chunk = 64 (round-5 config)
//   [0,512)               sLog (128 floats)
//   [1024, +18432)        A stage0 (128 rows x 72 bf16, 144B stride)
//   [19456, +18432)       B stage0
//   [37888, +18432)       A stage1
//   [56320, +18432)       B stage1
#define STAGE_BYTES 36864
#define A_OFF(s) (1024 + (s) * STAGE_BYTES)
#define B_OFF(s) (1024 + (s) * STAGE_BYTES + 18432)
#define SMEM_BYTES (1024 + 2 * STAGE_BYTES)   // 74752
#define LDB 144                                // row stride bytes (72 bf16)

// ---------------------------------------------------------------------------
// Prep: W2 -> bf16 K-major; also zero g_logits
// ---------------------------------------------------------------------------
__global__ __launch_bounds__(256) void k_prep_w2(const float* __restrict__ W) {
    int row = blockIdx.x, tid = threadIdx.x;
    const float4* src = (const float4*)(W + (size_t)row * (2 * Hn) + Hn);
    float4 f = src[tid];
    __nv_bfloat162* dst = (__nv_bfloat162*)(g_W2bf + (size_t)row * Hn);
    dst[2 * tid]     = __floats2bfloat162_rn(f.x, f.y);
    dst[2 * tid + 1] = __floats2bfloat162_rn(f.z, f.w);
    int gi = blockIdx.x * 256 + tid;
    if (gi < Bn * Sn) g_logits[gi] = 0.f;
}

// ---------------------------------------------------------------------------
// Prep: encT[b][s][k] = bf16(enc[b][k][s])  (64x64 tiles, vectorized)
// ---------------------------------------------------------------------------
__global__ __launch_bounds__(256) void k_prep_enc(const float* __restrict__ enc) {
    __shared__ float t[64 * 67];                 // [k][s], stride 67
    int b = blockIdx.z, k0 = blockIdx.y * 64, s0 = blockIdx.x * 64;
    int tid = threadIdx.x;
    const float* src = enc + ((size_t)b * Sn + k0) * Hn + s0;
#pragma unroll
    for (int it = 0; it < 4; it++) {
        int i = tid + it * 256;                  // 1024 float4 slots
        int r = i >> 4, c = i & 15;
        float4 f = *(const float4*)(src + (size_t)r * Hn + c * 4);
        float* tp = &t[r * 67 + c * 4];
        tp[0] = f.x; tp[1] = f.y; tp[2] = f.z; tp[3] = f.w;
    }
    __syncthreads();
    __nv_bfloat16* dst = g_encT + ((size_t)b * Sn + s0) * Hn + k0;
#pragma unroll
    for (int it = 0; it < 8; it++) {
        int i = tid + it * 256;                  // 2048 bf162 slots
        int srow = i >> 5, p = i & 31;
        __nv_bfloat162 v = __floats2bfloat162_rn(t[(2 * p) * 67 + srow],
                                                 t[(2 * p + 1) * 67 + srow]);
        *(__nv_bfloat162*)(dst + (size_t)srow * Hn + 2 * p) = v;
    }
}

// ---------------------------------------------------------------------------
// A1[b,h] = bias[h] + sum_k hidden[b,k] * W[h,k]  (one warp per output)
// ---------------------------------------------------------------------------
__global__ __launch_bounds__(256) void k_a1(const float* __restrict__ hidden,
                                            const float* __restrict__ W,
                                            const float* __restrict__ bias) {
    int gw = (blockIdx.x * 256 + threadIdx.x) >> 5;
    int lane = threadIdx.x & 31;
    int h = gw & (Hn - 1);
    int b = gw >> 10;
    const float* wr = W + (size_t)h * (2 * Hn);
    const float* hr = hidden + (size_t)b * Hn;
    float s = 0.f;
#pragma unroll 4
    for (int k = lane; k < Hn; k += 32) s += wr[k] * hr[k];
#pragma unroll
    for (int o = 16; o; o >>= 1) s += __shfl_xor_sync(0xffffffffu, s, o);
    if (lane == 0) g_A1[gw] = s + bias[h];
}

// ---------------------------------------------------------------------------
// chunk loader: A[128 x 64] from W2bf, B[128 x 64] from encT (bf16, cp.async)
// ---------------------------------------------------------------------------
__device__ __forceinline__ void load_chunk(int tid,
                                           const __nv_bfloat16* gW,
                                           const __nv_bfloat16* gE,
                                           int kc, uint32_t aBase, uint32_t bBase) {
#pragma unroll
    for (int t = 0; t < 4; t++) {
        int idx = tid + t * 256;
        int r = idx >> 3, c = idx & 7;
        CP_ASYNC16(aBase + r * LDB + c * 16, gW + (size_t)r * Hn + kc + c * 8);
    }
#pragma unroll
    for (int t = 0; t < 4; t++) {
        int idx = tid + t * 256;
        int r = idx >> 3, c = idx & 7;
        CP_ASYNC16(bBase + r * LDB + c * 16, gE + (size_t)r * Hn + kc + c * 8);
    }
    asm volatile("cp.async.commit_group;" ::: "memory");
}

// ---------------------------------------------------------------------------
// k_energy: one CTA per (b, h-tile=128, s-tile=128).
// D[h,s] = sum_k W2bf[h,k] * encT[b,s,k]  via mma.sync m16n8k16 bf16 (HMMA).
// 2-stage cp.async pipeline, K-chunk = 64 (round-5 operating point).
// Epilogue: logits[b,s] += sum_h v[h] * tanh(A1[b,h] + D[h,s])
// ---------------------------------------------------------------------------
__global__ __launch_bounds__(256, 2) void k_energy(const float* __restrict__ v) {
    extern __shared__ char smem[];
    uint32_t sb = smem_u32(smem);
    float* sLog = (float*)smem;

    const int tid = threadIdx.x;
    const int l   = tid & 31;
    const int w   = tid >> 5;
    const int wr  = w >> 1;     // 0..3 : h-subtile (32 rows)
    const int wc  = w & 1;      // 0..1 : s-subtile (64 cols)
    const int b   = blockIdx.z;
    const int hc  = blockIdx.y * 128;
    const int sc  = blockIdx.x * 128;

    if (tid < 128) sLog[tid] = 0.f;

    const __nv_bfloat16* gW = g_W2bf + (size_t)hc * Hn;
    const __nv_bfloat16* gE = g_encT + ((size_t)b * Sn + sc) * Hn;

    float acc[2][8][4];
#pragma unroll
    for (int mi = 0; mi < 2; mi++)
#pragma unroll
        for (int ni = 0; ni < 8; ni++)
#pragma unroll
            for (int j = 0; j < 4; j++) acc[mi][ni][j] = 0.f;

    // ldmatrix lane addressing (constant per thread)
    const int a_row  = l & 15;          // m row within 16
    const int a_kh   = (l >> 4) * 8;    // k half
    const int b_nr   = (l & 7) | ((l >> 4) << 3);  // n row within 16
    const int b_kh   = ((l >> 3) & 1) * 8;

    load_chunk(tid, gW, gE, 0, sb + A_OFF(0), sb + B_OFF(0));

    for (int i = 0; i < 16; i++) {
        int p = i & 1;
        if (i + 1 < 16) {
            load_chunk(tid, gW, gE, (i + 1) * 64, sb + A_OFF(p ^ 1), sb + B_OFF(p ^ 1));
            asm volatile("cp.async.wait_group 1;" ::: "memory");
        } else {
            asm volatile("cp.async.wait_group 0;" ::: "memory");
        }
        __syncthreads();

        uint32_t aT = sb + A_OFF(p);
        uint32_t bT = sb + B_OFF(p);
#pragma unroll
        for (int k16 = 0; k16 < 4; k16++) {
            uint32_t ar[2][4], br[4][4];
            int kb = (k16 * 16) * 2;   // byte offset of k16 within row
#pragma unroll
            for (int mi = 0; mi < 2; mi++)
                LDSM_X4(ar[mi], aT + (uint32_t)((wr * 32 + mi * 16 + a_row) * LDB) + kb + a_kh * 2);
#pragma unroll
            for (int g = 0; g < 4; g++)
                LDSM_X4(br[g], bT + (uint32_t)((wc * 64 + g * 16 + b_nr) * LDB) + kb + b_kh * 2);
#pragma unroll
            for (int mi = 0; mi < 2; mi++)
#pragma unroll
                for (int ni = 0; ni < 8; ni++)
                    MMA16816(acc[mi][ni], ar[mi], br[ni >> 1][(ni & 1) * 2],
                             br[ni >> 1][(ni & 1) * 2 + 1]);
        }
        __syncthreads();
    }

    // ---- epilogue: tanh + v-dot, reduce over h ----
    float a1v[2][2], vv[2][2];
#pragma unroll
    for (int mi = 0; mi < 2; mi++)
#pragma unroll
        for (int j = 0; j < 2; j++) {
            int h = hc + wr * 32 + mi * 16 + (l >> 2) + j * 8;
            a1v[mi][j] = g_A1[b * Hn + h];
            vv[mi][j]  = v[h];
        }

    float part[8][2];
#pragma unroll
    for (int ni = 0; ni < 8; ni++) { part[ni][0] = 0.f; part[ni][1] = 0.f; }
#pragma unroll
    for (int mi = 0; mi < 2; mi++)
#pragma unroll
        for (int ni = 0; ni < 8; ni++) {
            part[ni][0] += vv[mi][0] * fast_tanh(a1v[mi][0] + acc[mi][ni][0]);
            part[ni][1] += vv[mi][0] * fast_tanh(a1v[mi][0] + acc[mi][ni][1]);
            part[ni][0] += vv[mi][1] * fast_tanh(a1v[mi][1] + acc[mi][ni][2]);
            part[ni][1] += vv[mi][1] * fast_tanh(a1v[mi][1] + acc[mi][ni][3]);
        }
#pragma unroll
    for (int ni = 0; ni < 8; ni++)
#pragma unroll
        for (int e = 0; e < 2; e++) {
            float s = part[ni][e];
            s += __shfl_xor_sync(0xffffffffu, s, 4);
            s += __shfl_xor_sync(0xffffffffu, s, 8);
            s += __shfl_xor_sync(0xffffffffu, s, 16);
            if (l < 4) atomicAdd(&sLog[wc * 64 + ni * 8 + (l & 3) * 2 + e], s);
        }
    __syncthreads();
    if (tid < 128) atomicAdd(&g_logits[b * Sn + sc + tid], sLog[tid]);
}

// ---------------------------------------------------------------------------
// softmax over s per batch; writes scores output; zeros ctx for k_context
// ---------------------------------------------------------------------------
__global__ __launch_bounds__(256) void k_softmax(float* __restrict__ scores_out,
                                                 int write_out,
                                                 float* __restrict__ ctx) {
    __shared__ float red[8];
    int b = blockIdx.x, tid = threadIdx.x;
    int lane = tid & 31, wid = tid >> 5;
#pragma unroll
    for (int t = 0; t < 4; t++) ctx[b * Hn + tid + t * 256] = 0.f;
    float l[4];
    float m = -1e30f;
#pragma unroll
    for (int t = 0; t < 4; t++) {
        l[t] = g_logits[b * Sn + tid + t * 256];
        m = fmaxf(m, l[t]);
    }
#pragma unroll
    for (int o = 16; o; o >>= 1) m = fmaxf(m, __shfl_xor_sync(0xffffffffu, m, o));
    if (lane == 0) red[wid] = m;
    __syncthreads();
    if (wid == 0) {
        float x = red[lane & 7];
#pragma unroll
        for (int o = 4; o; o >>= 1) x = fmaxf(x, __shfl_xor_sync(0xffffffffu, x, o));
        if (lane == 0) red[0] = x;
    }
    __syncthreads();
    m = red[0];
    float s = 0.f;
#pragma unroll
    for (int t = 0; t < 4; t++) {
        l[t] = __expf(l[t] - m);
        s += l[t];
    }
#pragma unroll
    for (int o = 16; o; o >>= 1) s += __shfl_xor_sync(0xffffffffu, s, o);
    __syncthreads();
    if (lane == 0) red[wid] = s;
    __syncthreads();
    if (wid == 0) {
        float x = red[lane & 7];
#pragma unroll
        for (int o = 4; o; o >>= 1) x += __shfl_xor_sync(0xffffffffu, x, o);
        if (lane == 0) red[0] = x;
    }
    __syncthreads();
    float inv = 1.f / red[0];
#pragma unroll
    for (int t = 0; t < 4; t++) {
        float sv = l[t] * inv;
        g_scores[b * Sn + tid + t * 256] = sv;
        if (write_out) scores_out[b * Sn + tid + t * 256] = sv;
    }
}

// ---------------------------------------------------------------------------
// context[b,h] = sum_s scores[b,s] * enc[b,s,h]; s split 8 ways, atomicAdd
// ---------------------------------------------------------------------------
__global__ __launch_bounds__(256) void k_context(const float* __restrict__ enc,
                                                 float* __restrict__ out_ctx) {
    __shared__ float ssc[128];
    int hc = blockIdx.x * 256;
    int b  = blockIdx.y;
    int s0 = blockIdx.z * 128;
    int tid = threadIdx.x;
    if (tid < 128) ssc[tid] = g_scores[b * Sn + s0 + tid];
    __syncthreads();
    const float* e = enc + ((size_t)b * Sn + s0) * Hn + hc + tid;
    float a0 = 0.f, a1 = 0.f, a2 = 0.f, a3 = 0.f;
#pragma unroll 4
    for (int s = 0; s < 128; s += 4) {
        a0 += ssc[s]     * e[(size_t)s * Hn];
        a1 += ssc[s + 1] * e[(size_t)(s + 1) * Hn];
        a2 += ssc[s + 2] * e[(size_t)(s + 2) * Hn];
        a3 += ssc[s + 3] * e[(size_t)(s + 3) * Hn];
    }
    atomicAdd(&out_ctx[b * Hn + hc + tid], (a0 + a1) + (a2 + a3));
}

// ---------------------------------------------------------------------------
extern "C" void kernel_launch(void* const* d_in, const int* in_sizes, int n_in,
                              void* d_out, int out_size) {
    const float* hidden = (const float*)d_in[0];
    const float* enc    = (const float*)d_in[1];
    const float* W      = (const float*)d_in[2];
    const float* bias   = (const float*)d_in[3];
    const float* v      = (const float*)d_in[4];

    float* out = (float*)d_out;
    float* ctx = out;                 // context: [B, H]
    float* scr = out + Bn * Hn;       // scores:  [B, 1, S]
    int write_scores = (out_size >= Bn * Hn + Bn * Sn) ? 1 : 0;

    cudaFuncSetAttribute(k_energy, cudaFuncAttributeMaxDynamicSharedMemorySize, SMEM_BYTES);

    k_prep_w2<<<1024, 256>>>(W);
    k_prep_enc<<<dim3(16, 16, 32), 256>>>(enc);
    k_a1<<<(Bn * Hn) / 8, 256>>>(hidden, W, bias);

    k_energy<<<dim3(8, 8, 32), 256, SMEM_BYTES>>>(v);

    k_softmax<<<Bn, 256>>>(scr, write_scores, ctx);
    k_context<<<dim3(4, 32, 8), 256>>>(enc, ctx);
}

// round 12
// speedup vs baseline: 6.3972x; 1.0012x over previous
#include <cuda_runtime.h>
#include <cuda_bf16.h>
#include <stdint.h>
#include <math.h>

#define Bn 32
#define Hn 1024
#define Sn 1024

// ---------------- scratch (device globals; no allocation allowed) ----------
__device__ float g_A1[Bn * Hn];
__device__ float g_logits[Bn * Sn];
__device__ float g_scores[Bn * Sn];
__device__ __nv_bfloat16 g_W2bf[Hn * Hn];         // [h][k]  K-major
__device__ __nv_bfloat16 g_encT[Bn * Sn * Hn];    // [b][s][k] = enc[b][k][s]

// ---------------- helpers ---------------------------------------------------
__device__ __forceinline__ uint32_t smem_u32(const void* p) {
    uint32_t a;
    asm("{ .reg .u64 t; cvta.to.shared.u64 t, %1; cvt.u32.u64 %0, t; }" : "=r"(a) : "l"(p));
    return a;
}
__device__ __forceinline__ float fast_tanh(float x) {
    float y;
    asm("tanh.approx.f32 %0, %1;" : "=f"(y) : "f"(x));
    return y;
}
#define CP_ASYNC16(smem_a, gptr) \
    asm volatile("cp.async.cg.shared.global [%0], [%1], 16;" :: "r"(smem_a), "l"(gptr) : "memory")

#define LDSM_X4(r, addr) \
    asm volatile("ldmatrix.sync.aligned.m8n8.x4.shared.b16 {%0,%1,%2,%3}, [%4];" \
        : "=r"((r)[0]), "=r"((r)[1]), "=r"((r)[2]), "=r"((r)[3]) : "r"(addr))

#define MMA16816(d, a, b0, b1) \
    asm volatile("mma.sync.aligned.m16n8k16.row.col.f32.bf16.bf16.f32 " \
        "{%0,%1,%2,%3}, {%4,%5,%6,%7}, {%8,%9}, {%0,%1,%2,%3};" \
        : "+f"((d)[0]), "+f"((d)[1]), "+f"((d)[2]), "+f"((d)[3]) \
        : "r"((a)[0]), "r"((a)[1]), "r"((a)[2]), "r"((a)[3]), "r"(b0), "r"(b1))

// SMEM layout for k_energy: 3-stage pipeline, K-chunk = 64
//   [0,512)               sLog (128 floats)
//   stage s at 1024 + s*36864 : A[128 x 144B] then B[128 x 144B]
#define STAGE_BYTES 36864
#define A_OFF(s) (1024 + (s) * STAGE_BYTES)
#define B_OFF(s) (1024 + (s) * STAGE_BYTES + 18432)
#define SMEM_BYTES (1024 + 3 * STAGE_BYTES)   // 111616
#define LDB 144                                // row stride bytes (72 bf16)

// ---------------------------------------------------------------------------
// Prep: W2 -> bf16 K-major; also zero g_logits
// ---------------------------------------------------------------------------
__global__ __launch_bounds__(256) void k_prep_w2(const float* __restrict__ W) {
    int row = blockIdx.x, tid = threadIdx.x;
    const float4* src = (const float4*)(W + (size_t)row * (2 * Hn) + Hn);
    float4 f = src[tid];
    __nv_bfloat162* dst = (__nv_bfloat162*)(g_W2bf + (size_t)row * Hn);
    dst[2 * tid]     = __floats2bfloat162_rn(f.x, f.y);
    dst[2 * tid + 1] = __floats2bfloat162_rn(f.z, f.w);
    int gi = blockIdx.x * 256 + tid;
    if (gi < Bn * Sn) g_logits[gi] = 0.f;
}

// ---------------------------------------------------------------------------
// Prep: encT[b][s][k] = bf16(enc[b][k][s])  (64x64 tiles, vectorized)
// ---------------------------------------------------------------------------
__global__ __launch_bounds__(256) void k_prep_enc(const float* __restrict__ enc) {
    __shared__ float t[64 * 67];                 // [k][s], stride 67
    int b = blockIdx.z, k0 = blockIdx.y * 64, s0 = blockIdx.x * 64;
    int tid = threadIdx.x;
    const float* src = enc + ((size_t)b * Sn + k0) * Hn + s0;
#pragma unroll
    for (int it = 0; it < 4; it++) {
        int i = tid + it * 256;                  // 1024 float4 slots
        int r = i >> 4, c = i & 15;
        float4 f = *(const float4*)(src + (size_t)r * Hn + c * 4);
        float* tp = &t[r * 67 + c * 4];
        tp[0] = f.x; tp[1] = f.y; tp[2] = f.z; tp[3] = f.w;
    }
    __syncthreads();
    __nv_bfloat16* dst = g_encT + ((size_t)b * Sn + s0) * Hn + k0;
#pragma unroll
    for (int it = 0; it < 8; it++) {
        int i = tid + it * 256;                  // 2048 bf162 slots
        int srow = i >> 5, p = i & 31;
        __nv_bfloat162 v = __floats2bfloat162_rn(t[(2 * p) * 67 + srow],
                                                 t[(2 * p + 1) * 67 + srow]);
        *(__nv_bfloat162*)(dst + (size_t)srow * Hn + 2 * p) = v;
    }
}

// ---------------------------------------------------------------------------
// A1[b,h] = bias[h] + sum_k hidden[b,k] * W[h,k]  (one warp per output)
// ---------------------------------------------------------------------------
__global__ __launch_bounds__(256) void k_a1(const float* __restrict__ hidden,
                                            const float* __restrict__ W,
                                            const float* __restrict__ bias) {
    int gw = (blockIdx.x * 256 + threadIdx.x) >> 5;
    int lane = threadIdx.x & 31;
    int h = gw & (Hn - 1);
    int b = gw >> 10;
    const float* wr = W + (size_t)h * (2 * Hn);
    const float* hr = hidden + (size_t)b * Hn;
    float s = 0.f;
#pragma unroll 4
    for (int k = lane; k < Hn; k += 32) s += wr[k] * hr[k];
#pragma unroll
    for (int o = 16; o; o >>= 1) s += __shfl_xor_sync(0xffffffffu, s, o);
    if (lane == 0) g_A1[gw] = s + bias[h];
}

// ---------------------------------------------------------------------------
// chunk loader: A[128 x 64] from W2bf, B[128 x 64] from encT (bf16, cp.async)
// ---------------------------------------------------------------------------
__device__ __forceinline__ void load_chunk(int tid,
                                           const __nv_bfloat16* gW,
                                           const __nv_bfloat16* gE,
                                           int kc, uint32_t aBase, uint32_t bBase) {
#pragma unroll
    for (int t = 0; t < 4; t++) {
        int idx = tid + t * 256;
        int r = idx >> 3, c = idx & 7;
        CP_ASYNC16(aBase + r * LDB + c * 16, gW + (size_t)r * Hn + kc + c * 8);
    }
#pragma unroll
    for (int t = 0; t < 4; t++) {
        int idx = tid + t * 256;
        int r = idx >> 3, c = idx & 7;
        CP_ASYNC16(bBase + r * LDB + c * 16, gE + (size_t)r * Hn + kc + c * 8);
    }
    asm volatile("cp.async.commit_group;" ::: "memory");
}

// ---------------------------------------------------------------------------
// k_energy: one CTA per (b, h-tile=128, s-tile=128).
// D[h,s] = sum_k W2bf[h,k] * encT[b,s,k]  via mma.sync m16n8k16 bf16 (HMMA).
// 3-stage cp.async pipeline, K-chunk = 64, one barrier per chunk.
// Order per iter: wait_group -> __syncthreads -> issue prefetch -> compute.
// (wait BEFORE sync is required: wait_group only drains the calling thread's
//  groups; the sync makes every thread's chunk-i data visible to all.)
// Epilogue: logits[b,s] += sum_h v[h] * tanh(A1[b,h] + D[h,s])
// ---------------------------------------------------------------------------
__global__ __launch_bounds__(256, 2) void k_energy(const float* __restrict__ v) {
    extern __shared__ char smem[];
    uint32_t sb = smem_u32(smem);
    float* sLog = (float*)smem;

    const int tid = threadIdx.x;
    const int l   = tid & 31;
    const int w   = tid >> 5;
    const int wr  = w >> 1;     // 0..3 : h-subtile (32 rows)
    const int wc  = w & 1;      // 0..1 : s-subtile (64 cols)
    const int b   = blockIdx.z;
    const int hc  = blockIdx.y * 128;
    const int sc  = blockIdx.x * 128;

    if (tid < 128) sLog[tid] = 0.f;

    const __nv_bfloat16* gW = g_W2bf + (size_t)hc * Hn;
    const __nv_bfloat16* gE = g_encT + ((size_t)b * Sn + sc) * Hn;

    float acc[2][8][4];
#pragma unroll
    for (int mi = 0; mi < 2; mi++)
#pragma unroll
        for (int ni = 0; ni < 8; ni++)
#pragma unroll
            for (int j = 0; j < 4; j++) acc[mi][ni][j] = 0.f;

    // ldmatrix lane addressing (constant per thread)
    const int a_row  = l & 15;          // m row within 16
    const int a_kh   = (l >> 4) * 8;    // k half
    const int b_nr   = (l & 7) | ((l >> 4) << 3);  // n row within 16
    const int b_kh   = ((l >> 3) & 1) * 8;

    // preload stages 0,1 (chunks 0,1)
    load_chunk(tid, gW, gE, 0 * 64, sb + A_OFF(0), sb + B_OFF(0));
    load_chunk(tid, gW, gE, 1 * 64, sb + A_OFF(1), sb + B_OFF(1));

    for (int i = 0; i < 16; i++) {
        const int cur = i % 3;
        // 1) own chunk-i group complete (tail: drain everything)
        if (i < 15) {
            asm volatile("cp.async.wait_group 1;" ::: "memory");
        } else {
            asm volatile("cp.async.wait_group 0;" ::: "memory");
        }
        // 2) all threads' chunk-i data visible; all done computing chunk i-1
        __syncthreads();
        // 3) prefetch chunk i+2 into the slot freed at iter i-1
        if (i + 2 < 16) {
            load_chunk(tid, gW, gE, (i + 2) * 64,
                       sb + A_OFF((i + 2) % 3), sb + B_OFF((i + 2) % 3));
        }
        // 4) compute chunk i
        uint32_t aT = sb + A_OFF(cur);
        uint32_t bT = sb + B_OFF(cur);
#pragma unroll
        for (int k16 = 0; k16 < 4; k16++) {
            uint32_t ar[2][4], br[4][4];
            int kb = (k16 * 16) * 2;   // byte offset of k16 within row
#pragma unroll
            for (int mi = 0; mi < 2; mi++)
                LDSM_X4(ar[mi], aT + (uint32_t)((wr * 32 + mi * 16 + a_row) * LDB) + kb + a_kh * 2);
#pragma unroll
            for (int g = 0; g < 4; g++)
                LDSM_X4(br[g], bT + (uint32_t)((wc * 64 + g * 16 + b_nr) * LDB) + kb + b_kh * 2);
#pragma unroll
            for (int mi = 0; mi < 2; mi++)
#pragma unroll
                for (int ni = 0; ni < 8; ni++)
                    MMA16816(acc[mi][ni], ar[mi], br[ni >> 1][(ni & 1) * 2],
                             br[ni >> 1][(ni & 1) * 2 + 1]);
        }
    }

    // ---- epilogue: tanh + v-dot, reduce over h ----
    float a1v[2][2], vv[2][2];
#pragma unroll
    for (int mi = 0; mi < 2; mi++)
#pragma unroll
        for (int j = 0; j < 2; j++) {
            int h = hc + wr * 32 + mi * 16 + (l >> 2) + j * 8;
            a1v[mi][j] = g_A1[b * Hn + h];
            vv[mi][j]  = v[h];
        }

    float part[8][2];
#pragma unroll
    for (int ni = 0; ni < 8; ni++) { part[ni][0] = 0.f; part[ni][1] = 0.f; }
#pragma unroll
    for (int mi = 0; mi < 2; mi++)
#pragma unroll
        for (int ni = 0; ni < 8; ni++) {
            part[ni][0] += vv[mi][0] * fast_tanh(a1v[mi][0] + acc[mi][ni][0]);
            part[ni][1] += vv[mi][0] * fast_tanh(a1v[mi][0] + acc[mi][ni][1]);
            part[ni][0] += vv[mi][1] * fast_tanh(a1v[mi][1] + acc[mi][ni][2]);
            part[ni][1] += vv[mi][1] * fast_tanh(a1v[mi][1] + acc[mi][ni][3]);
        }
#pragma unroll
    for (int ni = 0; ni < 8; ni++)
#pragma unroll
        for (int e = 0; e < 2; e++) {
            float s = part[ni][e];
            s += __shfl_xor_sync(0xffffffffu, s, 4);
            s += __shfl_xor_sync(0xffffffffu, s, 8);
            s += __shfl_xor_sync(0xffffffffu, s, 16);
            if (l < 4) atomicAdd(&sLog[wc * 64 + ni * 8 + (l & 3) * 2 + e], s);
        }
    __syncthreads();
    if (tid < 128) atomicAdd(&g_logits[b * Sn + sc + tid], sLog[tid]);
}

// ---------------------------------------------------------------------------
// softmax over s per batch; writes scores output; zeros ctx for k_context
// ---------------------------------------------------------------------------
__global__ __launch_bounds__(256) void k_softmax(float* __restrict__ scores_out,
                                                 int write_out,
                                                 float* __restrict__ ctx) {
    __shared__ float red[8];
    int b = blockIdx.x, tid = threadIdx.x;
    int lane = tid & 31, wid = tid >> 5;
#pragma unroll
    for (int t = 0; t < 4; t++) ctx[b * Hn + tid + t * 256] = 0.f;
    float l[4];
    float m = -1e30f;
#pragma unroll
    for (int t = 0; t < 4; t++) {
        l[t] = g_logits[b * Sn + tid + t * 256];
        m = fmaxf(m, l[t]);
    }
#pragma unroll
    for (int o = 16; o; o >>= 1) m = fmaxf(m, __shfl_xor_sync(0xffffffffu, m, o));
    if (lane == 0) red[wid] = m;
    __syncthreads();
    if (wid == 0) {
        float x = red[lane & 7];
#pragma unroll
        for (int o = 4; o; o >>= 1) x = fmaxf(x, __shfl_xor_sync(0xffffffffu, x, o));
        if (lane == 0) red[0] = x;
    }
    __syncthreads();
    m = red[0];
    float s = 0.f;
#pragma unroll
    for (int t = 0; t < 4; t++) {
        l[t] = __expf(l[t] - m);
        s += l[t];
    }
#pragma unroll
    for (int o = 16; o; o >>= 1) s += __shfl_xor_sync(0xffffffffu, s, o);
    __syncthreads();
    if (lane == 0) red[wid] = s;
    __syncthreads();
    if (wid == 0) {
        float x = red[lane & 7];
#pragma unroll
        for (int o = 4; o; o >>= 1) x += __shfl_xor_sync(0xffffffffu, x, o);
        if (lane == 0) red[0] = x;
    }
    __syncthreads();
    float inv = 1.f / red[0];
#pragma unroll
    for (int t = 0; t < 4; t++) {
        float sv = l[t] * inv;
        g_scores[b * Sn + tid + t * 256] = sv;
        if (write_out) scores_out[b * Sn + tid + t * 256] = sv;
    }
}

// ---------------------------------------------------------------------------
// context[b,h] = sum_s scores[b,s] * enc[b,s,h]; s split 8 ways, atomicAdd
// ---------------------------------------------------------------------------
__global__ __launch_bounds__(256) void k_context(const float* __restrict__ enc,
                                                 float* __restrict__ out_ctx) {
    __shared__ float ssc[128];
    int hc = blockIdx.x * 256;
    int b  = blockIdx.y;
    int s0 = blockIdx.z * 128;
    int tid = threadIdx.x;
    if (tid < 128) ssc[tid] = g_scores[b * Sn + s0 + tid];
    __syncthreads();
    const float* e = enc + ((size_t)b * Sn + s0) * Hn + hc + tid;
    float a0 = 0.f, a1 = 0.f, a2 = 0.f, a3 = 0.f;
#pragma unroll 4
    for (int s = 0; s < 128; s += 4) {
        a0 += ssc[s]     * e[(size_t)s * Hn];
        a1 += ssc[s + 1] * e[(size_t)(s + 1) * Hn];
        a2 += ssc[s + 2] * e[(size_t)(s + 2) * Hn];
        a3 += ssc[s + 3] * e[(size_t)(s + 3) * Hn];
    }
    atomicAdd(&out_ctx[b * Hn + hc + tid], (a0 + a1) + (a2 + a3));
}

// ---------------------------------------------------------------------------
extern "C" void kernel_launch(void* const* d_in, const int* in_sizes, int n_in,
                              void* d_out, int out_size) {
    const float* hidden = (const float*)d_in[0];
    const float* enc    = (const float*)d_in[1];
    const float* W      = (const float*)d_in[2];
    const float* bias   = (const float*)d_in[3];
    const float* v      = (const float*)d_in[4];

    float* out = (float*)d_out;
    float* ctx = out;                 // context: [B, H]
    float* scr = out + Bn * Hn;       // scores:  [B, 1, S]
    int write_scores = (out_size >= Bn * Hn + Bn * Sn) ? 1 : 0;

    cudaFuncSetAttribute(k_energy, cudaFuncAttributeMaxDynamicSharedMemorySize, SMEM_BYTES);

    k_prep_w2<<<1024, 256>>>(W);
    k_prep_enc<<<dim3(16, 16, 32), 256>>>(enc);
    k_a1<<<(Bn * Hn) / 8, 256>>>(hidden, W, bias);

    k_energy<<<dim3(8, 8, 32), 256, SMEM_BYTES>>>(v);

    k_softmax<<<Bn, 256>>>(scr, write_scores, ctx);
    k_context<<<dim3(4, 32, 8), 256>>>(enc, ctx);
}

// round 14
// speedup vs baseline: 6.5711x; 1.0272x over previous
#include <cuda_runtime.h>
#include <cuda_bf16.h>
#include <stdint.h>
#include <math.h>

#define Bn 32
#define Hn 1024
#define Sn 1024

// ---------------- scratch (device globals; no allocation allowed) ----------
__device__ float g_A1[Bn * Hn];
__device__ float g_logits[Bn * Sn];
__device__ __nv_bfloat16 g_W2bf[Hn * Hn];         // [h][k]  K-major
__device__ __nv_bfloat16 g_encT[Bn * Sn * Hn];    // [b][s][k] = enc[b][k][s]

// ---------------- helpers ---------------------------------------------------
__device__ __forceinline__ uint32_t smem_u32(const void* p) {
    uint32_t a;
    asm("{ .reg .u64 t; cvta.to.shared.u64 t, %1; cvt.u32.u64 %0, t; }" : "=r"(a) : "l"(p));
    return a;
}
__device__ __forceinline__ float fast_tanh(float x) {
    float y;
    asm("tanh.approx.f32 %0, %1;" : "=f"(y) : "f"(x));
    return y;
}
#define CP_ASYNC16(smem_a, gptr) \
    asm volatile("cp.async.cg.shared.global [%0], [%1], 16;" :: "r"(smem_a), "l"(gptr) : "memory")

#define LDSM_X4(r, addr) \
    asm volatile("ldmatrix.sync.aligned.m8n8.x4.shared.b16 {%0,%1,%2,%3}, [%4];" \
        : "=r"((r)[0]), "=r"((r)[1]), "=r"((r)[2]), "=r"((r)[3]) : "r"(addr))

#define MMA16816(d, a, b0, b1) \
    asm volatile("mma.sync.aligned.m16n8k16.row.col.f32.bf16.bf16.f32 " \
        "{%0,%1,%2,%3}, {%4,%5,%6,%7}, {%8,%9}, {%0,%1,%2,%3};" \
        : "+f"((d)[0]), "+f"((d)[1]), "+f"((d)[2]), "+f"((d)[3]) \
        : "r"((a)[0]), "r"((a)[1]), "r"((a)[2]), "r"((a)[3]), "r"(b0), "r"(b1))

// SMEM layout for k_energy: 3-stage pipeline, K-chunk = 64
#define STAGE_BYTES 36864
#define A_OFF(s) (1024 + (s) * STAGE_BYTES)
#define B_OFF(s) (1024 + (s) * STAGE_BYTES + 18432)
#define SMEM_BYTES (1024 + 3 * STAGE_BYTES)   // 111616
#define LDB 144                                // row stride bytes (72 bf16)

// ---------------------------------------------------------------------------
// k_prep (merged): block ranges do independent prep work concurrently.
//   [0, 8192)      encT[b][s][k] = bf16(enc[b][k][s])  (64x64 tiles)
//   [8192, 9216)   W2 -> bf16 K-major; first 128 also zero g_logits
//   [9216, 10240)  A1[b,h] for one h, all 32 b (W1 row cached in smem)
//   [10240, 10272) zero ctx output region
// ---------------------------------------------------------------------------
__global__ __launch_bounds__(256) void k_prep(const float* __restrict__ enc,
                                              const float* __restrict__ W,
                                              const float* __restrict__ hidden,
                                              const float* __restrict__ bias,
                                              float* __restrict__ ctx_out) {
    __shared__ float sh[64 * 67];                // 17152 B
    const int bid = blockIdx.x, tid = threadIdx.x;

    if (bid < 8192) {
        // ---- encT transpose-convert ----
        int b = bid >> 8, k0 = ((bid >> 4) & 15) * 64, s0 = (bid & 15) * 64;
        const float* src = enc + ((size_t)b * Sn + k0) * Hn + s0;
#pragma unroll
        for (int it = 0; it < 4; it++) {
            int i = tid + it * 256;              // 1024 float4 slots
            int r = i >> 4, c = i & 15;
            float4 f = *(const float4*)(src + (size_t)r * Hn + c * 4);
            float* tp = &sh[r * 67 + c * 4];
            tp[0] = f.x; tp[1] = f.y; tp[2] = f.z; tp[3] = f.w;
        }
        __syncthreads();
        __nv_bfloat16* dst = g_encT + ((size_t)b * Sn + s0) * Hn + k0;
#pragma unroll
        for (int it = 0; it < 8; it++) {
            int i = tid + it * 256;              // 2048 bf162 slots
            int srow = i >> 5, p = i & 31;
            __nv_bfloat162 v = __floats2bfloat162_rn(sh[(2 * p) * 67 + srow],
                                                     sh[(2 * p + 1) * 67 + srow]);
            *(__nv_bfloat162*)(dst + (size_t)srow * Hn + 2 * p) = v;
        }
    } else if (bid < 9216) {
        // ---- W2 convert ----
        int row = bid - 8192;
        const float4* src = (const float4*)(W + (size_t)row * (2 * Hn) + Hn);
        float4 f = src[tid];
        __nv_bfloat162* dst = (__nv_bfloat162*)(g_W2bf + (size_t)row * Hn);
        dst[2 * tid]     = __floats2bfloat162_rn(f.x, f.y);
        dst[2 * tid + 1] = __floats2bfloat162_rn(f.z, f.w);
        if (row < 128) g_logits[row * 256 + tid] = 0.f;
    } else if (bid < 10240) {
        // ---- A1 for h = bid - 9216, all 32 b ----
        int h = bid - 9216;
        const float* wr = W + (size_t)h * (2 * Hn);
#pragma unroll
        for (int t = 0; t < 4; t++) sh[tid + t * 256] = wr[tid + t * 256];
        __syncthreads();
        int w = tid >> 5, lane = tid & 31;
        float bv = bias[h];
#pragma unroll
        for (int i = 0; i < 4; i++) {
            int b = w + i * 8;
            const float* hr = hidden + (size_t)b * Hn;
            float s = 0.f;
#pragma unroll 4
            for (int j = lane; j < Hn; j += 32) s += sh[j] * hr[j];
#pragma unroll
            for (int o = 16; o; o >>= 1) s += __shfl_xor_sync(0xffffffffu, s, o);
            if (lane == 0) g_A1[b * Hn + h] = s + bv;
        }
    } else {
        // ---- zero ctx region of output ----
        int b = bid - 10240;
        float4 z = make_float4(0.f, 0.f, 0.f, 0.f);
        ((float4*)(ctx_out + (size_t)b * Hn))[tid] = z;
    }
}

// ---------------------------------------------------------------------------
// chunk loader: A[128 x 64] from W2bf, B[128 x 64] from encT (bf16, cp.async)
// ---------------------------------------------------------------------------
__device__ __forceinline__ void load_chunk(int tid,
                                           const __nv_bfloat16* gW,
                                           const __nv_bfloat16* gE,
                                           int kc, uint32_t aBase, uint32_t bBase) {
#pragma unroll
    for (int t = 0; t < 4; t++) {
        int idx = tid + t * 256;
        int r = idx >> 3, c = idx & 7;
        CP_ASYNC16(aBase + r * LDB + c * 16, gW + (size_t)r * Hn + kc + c * 8);
    }
#pragma unroll
    for (int t = 0; t < 4; t++) {
        int idx = tid + t * 256;
        int r = idx >> 3, c = idx & 7;
        CP_ASYNC16(bBase + r * LDB + c * 16, gE + (size_t)r * Hn + kc + c * 8);
    }
    asm volatile("cp.async.commit_group;" ::: "memory");
}

// ---------------------------------------------------------------------------
// k_energy: one CTA per (b, h-tile=128, s-tile=128).   (UNCHANGED from r12)
// D[h,s] = sum_k W2bf[h,k] * encT[b,s,k]  via mma.sync m16n8k16 bf16 (HMMA).
// 3-stage cp.async pipeline, K-chunk = 64, one barrier per chunk.
// Epilogue: logits[b,s] += sum_h v[h] * tanh(A1[b,h] + D[h,s])
// ---------------------------------------------------------------------------
__global__ __launch_bounds__(256, 2) void k_energy(const float* __restrict__ v) {
    extern __shared__ char smem[];
    uint32_t sb = smem_u32(smem);
    float* sLog = (float*)smem;

    const int tid = threadIdx.x;
    const int l   = tid & 31;
    const int w   = tid >> 5;
    const int wr  = w >> 1;     // 0..3 : h-subtile (32 rows)
    const int wc  = w & 1;      // 0..1 : s-subtile (64 cols)
    const int b   = blockIdx.z;
    const int hc  = blockIdx.y * 128;
    const int sc  = blockIdx.x * 128;

    if (tid < 128) sLog[tid] = 0.f;

    const __nv_bfloat16* gW = g_W2bf + (size_t)hc * Hn;
    const __nv_bfloat16* gE = g_encT + ((size_t)b * Sn + sc) * Hn;

    float acc[2][8][4];
#pragma unroll
    for (int mi = 0; mi < 2; mi++)
#pragma unroll
        for (int ni = 0; ni < 8; ni++)
#pragma unroll
            for (int j = 0; j < 4; j++) acc[mi][ni][j] = 0.f;

    const int a_row  = l & 15;
    const int a_kh   = (l >> 4) * 8;
    const int b_nr   = (l & 7) | ((l >> 4) << 3);
    const int b_kh   = ((l >> 3) & 1) * 8;

    load_chunk(tid, gW, gE, 0 * 64, sb + A_OFF(0), sb + B_OFF(0));
    load_chunk(tid, gW, gE, 1 * 64, sb + A_OFF(1), sb + B_OFF(1));

    for (int i = 0; i < 16; i++) {
        const int cur = i % 3;
        if (i < 15) {
            asm volatile("cp.async.wait_group 1;" ::: "memory");
        } else {
            asm volatile("cp.async.wait_group 0;" ::: "memory");
        }
        __syncthreads();
        if (i + 2 < 16) {
            load_chunk(tid, gW, gE, (i + 2) * 64,
                       sb + A_OFF((i + 2) % 3), sb + B_OFF((i + 2) % 3));
        }
        uint32_t aT = sb + A_OFF(cur);
        uint32_t bT = sb + B_OFF(cur);
#pragma unroll
        for (int k16 = 0; k16 < 4; k16++) {
            uint32_t ar[2][4], br[4][4];
            int kb = (k16 * 16) * 2;
#pragma unroll
            for (int mi = 0; mi < 2; mi++)
                LDSM_X4(ar[mi], aT + (uint32_t)((wr * 32 + mi * 16 + a_row) * LDB) + kb + a_kh * 2);
#pragma unroll
            for (int g = 0; g < 4; g++)
                LDSM_X4(br[g], bT + (uint32_t)((wc * 64 + g * 16 + b_nr) * LDB) + kb + b_kh * 2);
#pragma unroll
            for (int mi = 0; mi < 2; mi++)
#pragma unroll
                for (int ni = 0; ni < 8; ni++)
                    MMA16816(acc[mi][ni], ar[mi], br[ni >> 1][(ni & 1) * 2],
                             br[ni >> 1][(ni & 1) * 2 + 1]);
        }
    }

    // ---- epilogue ----
    float a1v[2][2], vv[2][2];
#pragma unroll
    for (int mi = 0; mi < 2; mi++)
#pragma unroll
        for (int j = 0; j < 2; j++) {
            int h = hc + wr * 32 + mi * 16 + (l >> 2) + j * 8;
            a1v[mi][j] = g_A1[b * Hn + h];
            vv[mi][j]  = v[h];
        }

    float part[8][2];
#pragma unroll
    for (int ni = 0; ni < 8; ni++) { part[ni][0] = 0.f; part[ni][1] = 0.f; }
#pragma unroll
    for (int mi = 0; mi < 2; mi++)
#pragma unroll
        for (int ni = 0; ni < 8; ni++) {
            part[ni][0] += vv[mi][0] * fast_tanh(a1v[mi][0] + acc[mi][ni][0]);
            part[ni][1] += vv[mi][0] * fast_tanh(a1v[mi][0] + acc[mi][ni][1]);
            part[ni][0] += vv[mi][1] * fast_tanh(a1v[mi][1] + acc[mi][ni][2]);
            part[ni][1] += vv[mi][1] * fast_tanh(a1v[mi][1] + acc[mi][ni][3]);
        }
#pragma unroll
    for (int ni = 0; ni < 8; ni++)
#pragma unroll
        for (int e = 0; e < 2; e++) {
            float s = part[ni][e];
            s += __shfl_xor_sync(0xffffffffu, s, 4);
            s += __shfl_xor_sync(0xffffffffu, s, 8);
            s += __shfl_xor_sync(0xffffffffu, s, 16);
            if (l < 4) atomicAdd(&sLog[wc * 64 + ni * 8 + (l & 3) * 2 + e], s);
        }
    __syncthreads();
    if (tid < 128) atomicAdd(&g_logits[b * Sn + sc + tid], sLog[tid]);
}

// ---------------------------------------------------------------------------
// k_ctx_fused: per block (b, s-chunk of 128): recompute softmax from logits
// (cheap, identical across blocks), then context partial over its s range
// with float4 h-loads covering all 1024 h.  (y==0) blocks write scores out.
// ---------------------------------------------------------------------------
__global__ __launch_bounds__(256) void k_ctx_fused(const float* __restrict__ enc,
                                                   float* __restrict__ out_ctx,
                                                   float* __restrict__ scores_out,
                                                   int write_out) {
    __shared__ float ssc[Sn];
    __shared__ float red[8];
    const int b  = blockIdx.x;
    const int s0 = blockIdx.y * 128;
    const int tid = threadIdx.x;
    const int lane = tid & 31, wid = tid >> 5;

    // ---- block softmax over all 1024 logits ----
    float lv[4];
    float m = -1e30f;
#pragma unroll
    for (int t = 0; t < 4; t++) {
        lv[t] = g_logits[b * Sn + tid + t * 256];
        m = fmaxf(m, lv[t]);
    }
#pragma unroll
    for (int o = 16; o; o >>= 1) m = fmaxf(m, __shfl_xor_sync(0xffffffffu, m, o));
    if (lane == 0) red[wid] = m;
    __syncthreads();
    if (wid == 0) {
        float x = red[lane & 7];
#pragma unroll
        for (int o = 4; o; o >>= 1) x = fmaxf(x, __shfl_xor_sync(0xffffffffu, x, o));
        if (lane == 0) red[0] = x;
    }
    __syncthreads();
    m = red[0];
    float s = 0.f;
#pragma unroll
    for (int t = 0; t < 4; t++) {
        lv[t] = __expf(lv[t] - m);
        s += lv[t];
    }
#pragma unroll
    for (int o = 16; o; o >>= 1) s += __shfl_xor_sync(0xffffffffu, s, o);
    __syncthreads();
    if (lane == 0) red[wid] = s;
    __syncthreads();
    if (wid == 0) {
        float x = red[lane & 7];
#pragma unroll
        for (int o = 4; o; o >>= 1) x += __shfl_xor_sync(0xffffffffu, x, o);
        if (lane == 0) red[0] = x;
    }
    __syncthreads();
    float inv = 1.f / red[0];
#pragma unroll
    for (int t = 0; t < 4; t++) {
        float sv = lv[t] * inv;
        ssc[tid + t * 256] = sv;
        if (write_out && blockIdx.y == 0) scores_out[b * Sn + tid + t * 256] = sv;
    }
    __syncthreads();

    // ---- context partial: thread covers h = tid*4 .. tid*4+3 ----
    const float4* e = (const float4*)(enc + ((size_t)b * Sn + s0) * Hn) + tid;
    float4 acc = make_float4(0.f, 0.f, 0.f, 0.f);
#pragma unroll 4
    for (int si = 0; si < 128; si++) {
        float wsc = ssc[s0 + si];
        float4 f = e[(size_t)si * 256];
        acc.x += wsc * f.x;
        acc.y += wsc * f.y;
        acc.z += wsc * f.z;
        acc.w += wsc * f.w;
    }
    float* dst = out_ctx + (size_t)b * Hn + tid * 4;
    atomicAdd(dst + 0, acc.x);
    atomicAdd(dst + 1, acc.y);
    atomicAdd(dst + 2, acc.z);
    atomicAdd(dst + 3, acc.w);
}

// ---------------------------------------------------------------------------
extern "C" void kernel_launch(void* const* d_in, const int* in_sizes, int n_in,
                              void* d_out, int out_size) {
    const float* hidden = (const float*)d_in[0];
    const float* enc    = (const float*)d_in[1];
    const float* W      = (const float*)d_in[2];
    const float* bias   = (const float*)d_in[3];
    const float* v      = (const float*)d_in[4];

    float* out = (float*)d_out;
    float* ctx = out;                 // context: [B, H]
    float* scr = out + Bn * Hn;       // scores:  [B, 1, S]
    int write_scores = (out_size >= Bn * Hn + Bn * Sn) ? 1 : 0;

    cudaFuncSetAttribute(k_energy, cudaFuncAttributeMaxDynamicSharedMemorySize, SMEM_BYTES);

    k_prep<<<10272, 256>>>(enc, W, hidden, bias, ctx);

    k_energy<<<dim3(8, 8, 32), 256, SMEM_BYTES>>>(v);

    k_ctx_fused<<<dim3(32, 8), 256>>>(enc, ctx, scr, write_scores);
}

// round 16
// speedup vs baseline: 6.7064x; 1.0206x over previous
#include <cuda_runtime.h>
#include <cuda_bf16.h>
#include <stdint.h>
#include <math.h>

#define Bn 32
#define Hn 1024
#define Sn 1024

// ---------------- scratch (device globals; no allocation allowed) ----------
__device__ float g_A1[Bn * Hn];
__device__ float g_logits[Bn * Sn];
__device__ __nv_bfloat16 g_W2bf[Hn * Hn];         // [h][k]  K-major
__device__ __nv_bfloat16 g_encT[Bn * Sn * Hn];    // [b][s][k] = enc[b][k][s]

// ---------------- helpers ---------------------------------------------------
__device__ __forceinline__ uint32_t smem_u32(const void* p) {
    uint32_t a;
    asm("{ .reg .u64 t; cvta.to.shared.u64 t, %1; cvt.u32.u64 %0, t; }" : "=r"(a) : "l"(p));
    return a;
}
__device__ __forceinline__ float fast_tanh(float x) {
    float y;
    asm("tanh.approx.f32 %0, %1;" : "=f"(y) : "f"(x));
    return y;
}
__device__ __forceinline__ uint32_t pack_bf2(float a, float b) {
    __nv_bfloat162 t = __floats2bfloat162_rn(a, b);
    return *reinterpret_cast<uint32_t*>(&t);
}
#define CP_ASYNC16(smem_a, gptr) \
    asm volatile("cp.async.cg.shared.global [%0], [%1], 16;" :: "r"(smem_a), "l"(gptr) : "memory")

#define LDSM_X4(r, addr) \
    asm volatile("ldmatrix.sync.aligned.m8n8.x4.shared.b16 {%0,%1,%2,%3}, [%4];" \
        : "=r"((r)[0]), "=r"((r)[1]), "=r"((r)[2]), "=r"((r)[3]) : "r"(addr))

#define MMA16816(d, a, b0, b1) \
    asm volatile("mma.sync.aligned.m16n8k16.row.col.f32.bf16.bf16.f32 " \
        "{%0,%1,%2,%3}, {%4,%5,%6,%7}, {%8,%9}, {%0,%1,%2,%3};" \
        : "+f"((d)[0]), "+f"((d)[1]), "+f"((d)[2]), "+f"((d)[3]) \
        : "r"((a)[0]), "r"((a)[1]), "r"((a)[2]), "r"((a)[3]), "r"(b0), "r"(b1))

// SMEM layout for k_energy: 3-stage pipeline, K-chunk = 64
#define STAGE_BYTES 36864
#define A_OFF(s) (1024 + (s) * STAGE_BYTES)
#define B_OFF(s) (1024 + (s) * STAGE_BYTES + 18432)
#define SMEM_BYTES (1024 + 3 * STAGE_BYTES)   // 111616
#define LDB 144                                // row stride bytes (72 bf16)

// ---------------------------------------------------------------------------
// k_prep (merged): block ranges do independent prep work concurrently.
//   [0, 8192)      encT[b][s][k] = bf16(enc[b][k][s])  (64x64 tiles)
//   [8192, 9216)   W2 -> bf16 K-major; first 128 also zero g_logits
//   [9216, 10240)  A1[b,h] for one h, all 32 b (W1 row cached in smem)
//   [10240, 10272) zero ctx output region
// ---------------------------------------------------------------------------
__global__ __launch_bounds__(256) void k_prep(const float* __restrict__ enc,
                                              const float* __restrict__ W,
                                              const float* __restrict__ hidden,
                                              const float* __restrict__ bias,
                                              float* __restrict__ ctx_out) {
    __shared__ float sh[64 * 67];                // 17152 B
    const int bid = blockIdx.x, tid = threadIdx.x;

    if (bid < 8192) {
        // ---- encT transpose-convert ----
        int b = bid >> 8, k0 = ((bid >> 4) & 15) * 64, s0 = (bid & 15) * 64;
        const float* src = enc + ((size_t)b * Sn + k0) * Hn + s0;
#pragma unroll
        for (int it = 0; it < 4; it++) {
            int i = tid + it * 256;              // 1024 float4 slots
            int r = i >> 4, c = i & 15;
            float4 f = *(const float4*)(src + (size_t)r * Hn + c * 4);
            float* tp = &sh[r * 67 + c * 4];
            tp[0] = f.x; tp[1] = f.y; tp[2] = f.z; tp[3] = f.w;
        }
        __syncthreads();
        __nv_bfloat16* dst = g_encT + ((size_t)b * Sn + s0) * Hn + k0;
#pragma unroll
        for (int it = 0; it < 2; it++) {
            int i = tid + it * 256;              // 512 slots of 16B
            int srow = i >> 3, kg = i & 7;       // kg: group of 8 consecutive k
            const float* col = &sh[kg * 8 * 67 + srow];
            uint4 o;
            o.x = pack_bf2(col[0 * 67], col[1 * 67]);
            o.y = pack_bf2(col[2 * 67], col[3 * 67]);
            o.z = pack_bf2(col[4 * 67], col[5 * 67]);
            o.w = pack_bf2(col[6 * 67], col[7 * 67]);
            *(uint4*)(dst + (size_t)srow * Hn + kg * 8) = o;
        }
    } else if (bid < 9216) {
        // ---- W2 convert ----
        int row = bid - 8192;
        const float4* src = (const float4*)(W + (size_t)row * (2 * Hn) + Hn);
        float4 f = src[tid];
        __nv_bfloat162* dst = (__nv_bfloat162*)(g_W2bf + (size_t)row * Hn);
        dst[2 * tid]     = __floats2bfloat162_rn(f.x, f.y);
        dst[2 * tid + 1] = __floats2bfloat162_rn(f.z, f.w);
        if (row < 128) g_logits[row * 256 + tid] = 0.f;
    } else if (bid < 10240) {
        // ---- A1 for h = bid - 9216, all 32 b ----
        int h = bid - 9216;
        const float* wr = W + (size_t)h * (2 * Hn);
#pragma unroll
        for (int t = 0; t < 4; t++) sh[tid + t * 256] = wr[tid + t * 256];
        __syncthreads();
        int w = tid >> 5, lane = tid & 31;
        float bv = bias[h];
#pragma unroll
        for (int i = 0; i < 4; i++) {
            int b = w + i * 8;
            const float* hr = hidden + (size_t)b * Hn;
            float s = 0.f;
#pragma unroll 4
            for (int j = lane; j < Hn; j += 32) s += sh[j] * hr[j];
#pragma unroll
            for (int o = 16; o; o >>= 1) s += __shfl_xor_sync(0xffffffffu, s, o);
            if (lane == 0) g_A1[b * Hn + h] = s + bv;
        }
    } else {
        // ---- zero ctx region of output ----
        int b = bid - 10240;
        float4 z = make_float4(0.f, 0.f, 0.f, 0.f);
        ((float4*)(ctx_out + (size_t)b * Hn))[tid] = z;
    }
}

// ---------------------------------------------------------------------------
// chunk loader: A[128 x 64] from W2bf, B[128 x 64] from encT (bf16, cp.async)
// ---------------------------------------------------------------------------
__device__ __forceinline__ void load_chunk(int tid,
                                           const __nv_bfloat16* gW,
                                           const __nv_bfloat16* gE,
                                           int kc, uint32_t aBase, uint32_t bBase) {
#pragma unroll
    for (int t = 0; t < 4; t++) {
        int idx = tid + t * 256;
        int r = idx >> 3, c = idx & 7;
        CP_ASYNC16(aBase + r * LDB + c * 16, gW + (size_t)r * Hn + kc + c * 8);
    }
#pragma unroll
    for (int t = 0; t < 4; t++) {
        int idx = tid + t * 256;
        int r = idx >> 3, c = idx & 7;
        CP_ASYNC16(bBase + r * LDB + c * 16, gE + (size_t)r * Hn + kc + c * 8);
    }
    asm volatile("cp.async.commit_group;" ::: "memory");
}

// ---------------------------------------------------------------------------
// k_energy: one CTA per (b, h-tile=128, s-tile=128).   (UNCHANGED)
// D[h,s] = sum_k W2bf[h,k] * encT[b,s,k]  via mma.sync m16n8k16 bf16 (HMMA).
// 3-stage cp.async pipeline, K-chunk = 64, one barrier per chunk.
// Epilogue: logits[b,s] += sum_h v[h] * tanh(A1[b,h] + D[h,s])
// ---------------------------------------------------------------------------
__global__ __launch_bounds__(256, 2) void k_energy(const float* __restrict__ v) {
    extern __shared__ char smem[];
    uint32_t sb = smem_u32(smem);
    float* sLog = (float*)smem;

    const int tid = threadIdx.x;
    const int l   = tid & 31;
    const int w   = tid >> 5;
    const int wr  = w >> 1;     // 0..3 : h-subtile (32 rows)
    const int wc  = w & 1;      // 0..1 : s-subtile (64 cols)
    const int b   = blockIdx.z;
    const int hc  = blockIdx.y * 128;
    const int sc  = blockIdx.x * 128;

    if (tid < 128) sLog[tid] = 0.f;

    const __nv_bfloat16* gW = g_W2bf + (size_t)hc * Hn;
    const __nv_bfloat16* gE = g_encT + ((size_t)b * Sn + sc) * Hn;

    float acc[2][8][4];
#pragma unroll
    for (int mi = 0; mi < 2; mi++)
#pragma unroll
        for (int ni = 0; ni < 8; ni++)
#pragma unroll
            for (int j = 0; j < 4; j++) acc[mi][ni][j] = 0.f;

    const int a_row  = l & 15;
    const int a_kh   = (l >> 4) * 8;
    const int b_nr   = (l & 7) | ((l >> 4) << 3);
    const int b_kh   = ((l >> 3) & 1) * 8;

    load_chunk(tid, gW, gE, 0 * 64, sb + A_OFF(0), sb + B_OFF(0));
    load_chunk(tid, gW, gE, 1 * 64, sb + A_OFF(1), sb + B_OFF(1));

    for (int i = 0; i < 16; i++) {
        const int cur = i % 3;
        if (i < 15) {
            asm volatile("cp.async.wait_group 1;" ::: "memory");
        } else {
            asm volatile("cp.async.wait_group 0;" ::: "memory");
        }
        __syncthreads();
        if (i + 2 < 16) {
            load_chunk(tid, gW, gE, (i + 2) * 64,
                       sb + A_OFF((i + 2) % 3), sb + B_OFF((i + 2) % 3));
        }
        uint32_t aT = sb + A_OFF(cur);
        uint32_t bT = sb + B_OFF(cur);
#pragma unroll
        for (int k16 = 0; k16 < 4; k16++) {
            uint32_t ar[2][4], br[4][4];
            int kb = (k16 * 16) * 2;
#pragma unroll
            for (int mi = 0; mi < 2; mi++)
                LDSM_X4(ar[mi], aT + (uint32_t)((wr * 32 + mi * 16 + a_row) * LDB) + kb + a_kh * 2);
#pragma unroll
            for (int g = 0; g < 4; g++)
                LDSM_X4(br[g], bT + (uint32_t)((wc * 64 + g * 16 + b_nr) * LDB) + kb + b_kh * 2);
#pragma unroll
            for (int mi = 0; mi < 2; mi++)
#pragma unroll
                for (int ni = 0; ni < 8; ni++)
                    MMA16816(acc[mi][ni], ar[mi], br[ni >> 1][(ni & 1) * 2],
                             br[ni >> 1][(ni & 1) * 2 + 1]);
        }
    }

    // ---- epilogue ----
    float a1v[2][2], vv[2][2];
#pragma unroll
    for (int mi = 0; mi < 2; mi++)
#pragma unroll
        for (int j = 0; j < 2; j++) {
            int h = hc + wr * 32 + mi * 16 + (l >> 2) + j * 8;
            a1v[mi][j] = g_A1[b * Hn + h];
            vv[mi][j]  = v[h];
        }

    float part[8][2];
#pragma unroll
    for (int ni = 0; ni < 8; ni++) { part[ni][0] = 0.f; part[ni][1] = 0.f; }
#pragma unroll
    for (int mi = 0; mi < 2; mi++)
#pragma unroll
        for (int ni = 0; ni < 8; ni++) {
            part[ni][0] += vv[mi][0] * fast_tanh(a1v[mi][0] + acc[mi][ni][0]);
            part[ni][1] += vv[mi][0] * fast_tanh(a1v[mi][0] + acc[mi][ni][1]);
            part[ni][0] += vv[mi][1] * fast_tanh(a1v[mi][1] + acc[mi][ni][2]);
            part[ni][1] += vv[mi][1] * fast_tanh(a1v[mi][1] + acc[mi][ni][3]);
        }
#pragma unroll
    for (int ni = 0; ni < 8; ni++)
#pragma unroll
        for (int e = 0; e < 2; e++) {
            float s = part[ni][e];
            s += __shfl_xor_sync(0xffffffffu, s, 4);
            s += __shfl_xor_sync(0xffffffffu, s, 8);
            s += __shfl_xor_sync(0xffffffffu, s, 16);
            if (l < 4) atomicAdd(&sLog[wc * 64 + ni * 8 + (l & 3) * 2 + e], s);
        }
    __syncthreads();
    if (tid < 128) atomicAdd(&g_logits[b * Sn + sc + tid], sLog[tid]);
}

// ---------------------------------------------------------------------------
// k_ctx_fused: per block (b, s-chunk of 64): recompute softmax from logits
// (cheap, identical across blocks), then context partial over its s range
// with float4 h-loads covering all 1024 h.  (y==0) blocks write scores out.
// ---------------------------------------------------------------------------
__global__ __launch_bounds__(256) void k_ctx_fused(const float* __restrict__ enc,
                                                   float* __restrict__ out_ctx,
                                                   float* __restrict__ scores_out,
                                                   int write_out) {
    __shared__ float ssc[Sn];
    __shared__ float red[8];
    const int b  = blockIdx.x;
    const int s0 = blockIdx.y * 64;
    const int tid = threadIdx.x;
    const int lane = tid & 31, wid = tid >> 5;

    // ---- block softmax over all 1024 logits ----
    float lv[4];
    float m = -1e30f;
#pragma unroll
    for (int t = 0; t < 4; t++) {
        lv[t] = g_logits[b * Sn + tid + t * 256];
        m = fmaxf(m, lv[t]);
    }
#pragma unroll
    for (int o = 16; o; o >>= 1) m = fmaxf(m, __shfl_xor_sync(0xffffffffu, m, o));
    if (lane == 0) red[wid] = m;
    __syncthreads();
    if (wid == 0) {
        float x = red[lane & 7];
#pragma unroll
        for (int o = 4; o; o >>= 1) x = fmaxf(x, __shfl_xor_sync(0xffffffffu, x, o));
        if (lane == 0) red[0] = x;
    }
    __syncthreads();
    m = red[0];
    float s = 0.f;
#pragma unroll
    for (int t = 0; t < 4; t++) {
        lv[t] = __expf(lv[t] - m);
        s += lv[t];
    }
#pragma unroll
    for (int o = 16; o; o >>= 1) s += __shfl_xor_sync(0xffffffffu, s, o);
    __syncthreads();
    if (lane == 0) red[wid] = s;
    __syncthreads();
    if (wid == 0) {
        float x = red[lane & 7];
#pragma unroll
        for (int o = 4; o; o >>= 1) x += __shfl_xor_sync(0xffffffffu, x, o);
        if (lane == 0) red[0] = x;
    }
    __syncthreads();
    float inv = 1.f / red[0];
#pragma unroll
    for (int t = 0; t < 4; t++) {
        float sv = lv[t] * inv;
        ssc[tid + t * 256] = sv;
        if (write_out && blockIdx.y == 0) scores_out[b * Sn + tid + t * 256] = sv;
    }
    __syncthreads();

    // ---- context partial: thread covers h = tid*4 .. tid*4+3 ----
    const float4* e = (const float4*)(enc + ((size_t)b * Sn + s0) * Hn) + tid;
    float4 acc = make_float4(0.f, 0.f, 0.f, 0.f);
#pragma unroll 8
    for (int si = 0; si < 64; si++) {
        float wsc = ssc[s0 + si];
        float4 f = e[(size_t)si * 256];
        acc.x += wsc * f.x;
        acc.y += wsc * f.y;
        acc.z += wsc * f.z;
        acc.w += wsc * f.w;
    }
    float* dst = out_ctx + (size_t)b * Hn + tid * 4;
    atomicAdd(dst + 0, acc.x);
    atomicAdd(dst + 1, acc.y);
    atomicAdd(dst + 2, acc.z);
    atomicAdd(dst + 3, acc.w);
}

// ---------------------------------------------------------------------------
extern "C" void kernel_launch(void* const* d_in, const int* in_sizes, int n_in,
                              void* d_out, int out_size) {
    const float* hidden = (const float*)d_in[0];
    const float* enc    = (const float*)d_in[1];
    const float* W      = (const float*)d_in[2];
    const float* bias   = (const float*)d_in[3];
    const float* v      = (const float*)d_in[4];

    float* out = (float*)d_out;
    float* ctx = out;                 // context: [B, H]
    float* scr = out + Bn * Hn;       // scores:  [B, 1, S]
    int write_scores = (out_size >= Bn * Hn + Bn * Sn) ? 1 : 0;

    cudaFuncSetAttribute(k_energy, cudaFuncAttributeMaxDynamicSharedMemorySize, SMEM_BYTES);

    k_prep<<<10272, 256>>>(enc, W, hidden, bias, ctx);

    k_energy<<<dim3(8, 8, 32), 256, SMEM_BYTES>>>(v);

    k_ctx_fused<<<dim3(32, 16), 256>>>(enc, ctx, scr, write_scores);
}